// round 1
// baseline (speedup 1.0000x reference)
#include <cuda_runtime.h>
#include <math.h>

// Problem constants (fixed shapes)
#define BATCH 2
#define SEQ   2048
#define DM    1024
#define NH    16
#define DH    64
#define MROWS (BATCH*SEQ)          // 4096

// Scratch (device globals; allocation-free)
__device__ float g_Q[BATCH*NH*SEQ*DH];
__device__ float g_K[BATCH*NH*SEQ*DH];
__device__ float g_V[BATCH*NH*SEQ*DH];
__device__ float g_ATT[MROWS*DM];

// ---------------------------------------------------------------------------
// SGEMM 128x128x8, 256 threads, 8x8 microtile, fused bias + output remap.
// mode 0: C index remapped to [B, H, S, dh]  (for Q/K/V projections)
// mode 1: plain row-major [M, N]
// ---------------------------------------------------------------------------
#define GM_BM 128
#define GM_BN 128
#define GM_BK 8

__global__ void __launch_bounds__(256) sgemm_bias(
    const float* __restrict__ A, const float* __restrict__ B,
    const float* __restrict__ bias, float* __restrict__ C,
    int M, int N, int K, int mode)
{
    __shared__ float As[GM_BK][GM_BM];
    __shared__ float Bs[GM_BK][GM_BN];

    const int tid = threadIdx.x;
    const int bm = blockIdx.y, bn = blockIdx.x;
    const int tr = (tid >> 4) * 8;     // row offset in tile (0..120)
    const int tc = (tid & 15) * 8;     // col offset in tile

    const int aRow = tid >> 1;         // 0..127
    const int aCol = (tid & 1) * 4;    // 0 or 4
    const int bRow = tid >> 5;         // 0..7
    const int bCol = (tid & 31) * 4;   // 0..124

    const float* Ag = A + (size_t)(bm * GM_BM) * K;
    const float* Bg = B + bn * GM_BN;

    float acc[8][8];
#pragma unroll
    for (int i = 0; i < 8; i++)
#pragma unroll
        for (int j = 0; j < 8; j++) acc[i][j] = 0.f;

    for (int k0 = 0; k0 < K; k0 += GM_BK) {
        float4 av = *(const float4*)(Ag + (size_t)aRow * K + k0 + aCol);
        As[aCol + 0][aRow] = av.x;
        As[aCol + 1][aRow] = av.y;
        As[aCol + 2][aRow] = av.z;
        As[aCol + 3][aRow] = av.w;
        float4 bv = *(const float4*)(Bg + (size_t)(k0 + bRow) * N + bCol);
        *(float4*)(&Bs[bRow][bCol]) = bv;
        __syncthreads();

#pragma unroll
        for (int k = 0; k < GM_BK; k++) {
            float ra[8], rb[8];
            *(float4*)(&ra[0]) = *(const float4*)(&As[k][tr]);
            *(float4*)(&ra[4]) = *(const float4*)(&As[k][tr + 4]);
            *(float4*)(&rb[0]) = *(const float4*)(&Bs[k][tc]);
            *(float4*)(&rb[4]) = *(const float4*)(&Bs[k][tc + 4]);
#pragma unroll
            for (int i = 0; i < 8; i++)
#pragma unroll
                for (int j = 0; j < 8; j++)
                    acc[i][j] += ra[i] * rb[j];
        }
        __syncthreads();
    }

#pragma unroll
    for (int i = 0; i < 8; i++) {
        const int m = bm * GM_BM + tr + i;
#pragma unroll
        for (int j = 0; j < 8; j++) {
            const int n = bn * GM_BN + tc + j;
            const float v = acc[i][j] + bias[n];
            size_t oidx;
            if (mode == 0) {
                const int b = m >> 11, s = m & 2047;
                const int h = n >> 6,  d = n & 63;
                oidx = ((size_t)(b * NH + h) * SEQ + s) * DH + d;
            } else {
                oidx = (size_t)m * N + n;
            }
            C[oidx] = v;
        }
    }
}

// ---------------------------------------------------------------------------
// Flash attention, fp32. Q/K/V in [B,H,S,dh]. Output in [B,S,H*dh].
// BQ=64 query rows per block, BK=64 key tile, online softmax.
// Threads 16x16; each thread: 4 q-rows x 4 cols microtile.
// pH bias is constant along softmax axis -> dropped (identity).
// ---------------------------------------------------------------------------
#define FA_BQ 64
#define FA_BK 64
#define FA_STR 68   // smem row stride (floats), float4-aligned, conflict-light

__global__ void __launch_bounds__(256) flash_attn(
    const float* __restrict__ Q, const float* __restrict__ K,
    const float* __restrict__ V, float* __restrict__ Out)
{
    extern __shared__ float sm[];
    float* Qt = sm;                    // [DH][FA_STR] : Qt[d][r], pre-scaled
    float* Kt = sm + 64 * FA_STR;      // [DH][FA_STR] : Kt[d][c]
    float* Vs = sm + 2 * 64 * FA_STR;  // [FA_BK][FA_STR] : Vs[c][dh]
    float* Pt = sm + 3 * 64 * FA_STR;  // [FA_BK][FA_STR] : Pt[c][r]

    const int tid = threadIdx.x;
    const int ty = tid >> 4, tx = tid & 15;
    const int r0 = ty * 4;             // q-row offset in tile
    const int c0 = tx * 4;             // col offset (k-col / dh-col)

    const int q0 = blockIdx.x * FA_BQ;
    const int bh = blockIdx.y;         // b*NH + h
    const int b = bh >> 4, h = bh & 15;

    const float* Qg = Q + (size_t)bh * SEQ * DH;
    const float* Kg = K + (size_t)bh * SEQ * DH;
    const float* Vg = V + (size_t)bh * SEQ * DH;

    const float scale = 0.125f;        // 1/sqrt(64)

    // Load Q tile, transposed into Qt[d][r], scaled.
    for (int i = tid; i < FA_BQ * (DH / 4); i += 256) {
        const int r = i >> 4;
        const int c = (i & 15) << 2;
        float4 v = *(const float4*)(Qg + (size_t)(q0 + r) * DH + c);
        Qt[(c + 0) * FA_STR + r] = v.x * scale;
        Qt[(c + 1) * FA_STR + r] = v.y * scale;
        Qt[(c + 2) * FA_STR + r] = v.z * scale;
        Qt[(c + 3) * FA_STR + r] = v.w * scale;
    }

    float m[4], l[4], o[4][4];
#pragma unroll
    for (int i = 0; i < 4; i++) {
        m[i] = -INFINITY; l[i] = 0.f;
#pragma unroll
        for (int j = 0; j < 4; j++) o[i][j] = 0.f;
    }

    for (int kt = 0; kt < SEQ / FA_BK; kt++) {
        const int k0 = kt * FA_BK;
        __syncthreads();  // protect Kt/Vs/Pt from previous iteration readers

        // Load K tile transposed -> Kt[d][c]; V tile direct -> Vs[c][d]
        for (int i = tid; i < FA_BK * (DH / 4); i += 256) {
            const int r = i >> 4;
            const int c = (i & 15) << 2;
            float4 kv = *(const float4*)(Kg + (size_t)(k0 + r) * DH + c);
            Kt[(c + 0) * FA_STR + r] = kv.x;
            Kt[(c + 1) * FA_STR + r] = kv.y;
            Kt[(c + 2) * FA_STR + r] = kv.z;
            Kt[(c + 3) * FA_STR + r] = kv.w;
            float4 vv = *(const float4*)(Vg + (size_t)(k0 + r) * DH + c);
            *(float4*)(&Vs[r * FA_STR + c]) = vv;
        }
        __syncthreads();

        // GEMM1: s[r][c] = sum_d Qt[d][r0+r] * Kt[d][c0+c]
        float s[4][4];
#pragma unroll
        for (int i = 0; i < 4; i++)
#pragma unroll
            for (int j = 0; j < 4; j++) s[i][j] = 0.f;

#pragma unroll 8
        for (int d = 0; d < DH; d++) {
            float4 qa = *(const float4*)(&Qt[d * FA_STR + r0]);
            float4 kb = *(const float4*)(&Kt[d * FA_STR + c0]);
            const float qr[4] = {qa.x, qa.y, qa.z, qa.w};
            const float kc[4] = {kb.x, kb.y, kb.z, kb.w};
#pragma unroll
            for (int i = 0; i < 4; i++)
#pragma unroll
                for (int j = 0; j < 4; j++)
                    s[i][j] += qr[i] * kc[j];
        }

        // Online softmax (row reduce across 16 lanes of the row group)
#pragma unroll
        for (int rr = 0; rr < 4; rr++) {
            float mt = fmaxf(fmaxf(s[rr][0], s[rr][1]), fmaxf(s[rr][2], s[rr][3]));
#pragma unroll
            for (int off = 8; off >= 1; off >>= 1)
                mt = fmaxf(mt, __shfl_xor_sync(0xffffffffu, mt, off, 16));
            const float mn = fmaxf(m[rr], mt);
            const float corr = __expf(m[rr] - mn);
            float ls = 0.f;
#pragma unroll
            for (int cc = 0; cc < 4; cc++) {
                const float p = __expf(s[rr][cc] - mn);
                s[rr][cc] = p;
                ls += p;
            }
#pragma unroll
            for (int off = 8; off >= 1; off >>= 1)
                ls += __shfl_xor_sync(0xffffffffu, ls, off, 16);
            l[rr] = l[rr] * corr + ls;
            m[rr] = mn;
#pragma unroll
            for (int j = 0; j < 4; j++) o[rr][j] *= corr;
        }

        // Write P transposed: Pt[c][r]
#pragma unroll
        for (int cc = 0; cc < 4; cc++)
#pragma unroll
            for (int rr = 0; rr < 4; rr++)
                Pt[(c0 + cc) * FA_STR + (r0 + rr)] = s[rr][cc];
        __syncthreads();

        // GEMM2: o[r][j] += sum_c Pt[c][r0+r] * Vs[c][c0+j]
#pragma unroll 8
        for (int c = 0; c < FA_BK; c++) {
            float4 pv = *(const float4*)(&Pt[c * FA_STR + r0]);
            float4 vv = *(const float4*)(&Vs[c * FA_STR + c0]);
            const float pr[4] = {pv.x, pv.y, pv.z, pv.w};
            const float vc[4] = {vv.x, vv.y, vv.z, vv.w};
#pragma unroll
            for (int i = 0; i < 4; i++)
#pragma unroll
                for (int j = 0; j < 4; j++)
                    o[i][j] += pr[i] * vc[j];
        }
    }

    // Epilogue: normalize and write in [B, S, H*dh] layout
#pragma unroll
    for (int rr = 0; rr < 4; rr++) {
        const float inv = 1.f / l[rr];
        const int row = q0 + r0 + rr;
        float4 out;
        out.x = o[rr][0] * inv;
        out.y = o[rr][1] * inv;
        out.z = o[rr][2] * inv;
        out.w = o[rr][3] * inv;
        *(float4*)(&Out[((size_t)b * SEQ + row) * DM + h * DH + c0]) = out;
    }
}

// ---------------------------------------------------------------------------
// Launch
// ---------------------------------------------------------------------------
extern "C" void kernel_launch(void* const* d_in, const int* in_sizes, int n_in,
                              void* d_out, int out_size)
{
    const float* x  = (const float*)d_in[0];
    // d_in[1] = pH : constant along softmax axis -> provably no effect
    const float* Wq = (const float*)d_in[2];
    const float* bq = (const float*)d_in[3];
    const float* Wk = (const float*)d_in[4];
    const float* bk = (const float*)d_in[5];
    const float* Wv = (const float*)d_in[6];
    const float* bv = (const float*)d_in[7];
    const float* Wo = (const float*)d_in[8];
    const float* bo = (const float*)d_in[9];
    float* out = (float*)d_out;

    float *qp, *kp, *vp, *ap;
    cudaGetSymbolAddress((void**)&qp, g_Q);
    cudaGetSymbolAddress((void**)&kp, g_K);
    cudaGetSymbolAddress((void**)&vp, g_V);
    cudaGetSymbolAddress((void**)&ap, g_ATT);

    const int smem_fa = 4 * 64 * FA_STR * sizeof(float);  // 69632 bytes
    cudaFuncSetAttribute(flash_attn, cudaFuncAttributeMaxDynamicSharedMemorySize, smem_fa);

    dim3 gg(DM / GM_BN, MROWS / GM_BM);   // (8, 32)
    sgemm_bias<<<gg, 256>>>(x, Wq, bq, qp, MROWS, DM, DM, 0);
    sgemm_bias<<<gg, 256>>>(x, Wk, bk, kp, MROWS, DM, DM, 0);
    sgemm_bias<<<gg, 256>>>(x, Wv, bv, vp, MROWS, DM, DM, 0);

    dim3 ga(SEQ / FA_BQ, BATCH * NH);     // (32, 32)
    flash_attn<<<ga, 256, smem_fa>>>(qp, kp, vp, ap);

    sgemm_bias<<<gg, 256>>>(ap, Wo, bo, out, MROWS, DM, DM, 1);
}

// round 3
// speedup vs baseline: 1.6593x; 1.6593x over previous
#include <cuda_runtime.h>
#include <math.h>
#include <stdint.h>

// Problem constants (fixed shapes)
#define BATCH 2
#define SEQ   2048
#define DM    1024
#define NH    16
#define DH    64
#define MROWS (BATCH*SEQ)          // 4096

// Scratch (device globals; allocation-free)
__device__ float g_Q[BATCH*NH*SEQ*DH];
__device__ float g_K[BATCH*NH*SEQ*DH];
__device__ float g_V[BATCH*NH*SEQ*DH];
__device__ float g_ATT[MROWS*DM];
__device__ float g_WT[4*DM*DM];    // transposed weights (K-major [N,K])

// ===========================================================================
// Helpers: cp.async + tf32 mma.sync (all baseline sm_80+ PTX, no 'a' features)
// ===========================================================================
__device__ __forceinline__ void cp16(uint32_t s, const void* g) {
    asm volatile("cp.async.cg.shared.global [%0], [%1], 16;" :: "r"(s), "l"(g));
}
#define CP_COMMIT() asm volatile("cp.async.commit_group;" ::: "memory")
#define CP_WAIT(N)  asm volatile("cp.async.wait_group %0;" :: "n"(N) : "memory")

__device__ __forceinline__ uint32_t f2tf32(float f) {
    uint32_t r;
    asm("cvt.rna.tf32.f32 %0, %1;" : "=r"(r) : "f"(f));
    return r;
}

__device__ __forceinline__ void mma_tf32(float c[4], const uint32_t a[4], const uint32_t b[2]) {
    asm volatile(
        "mma.sync.aligned.m16n8k8.row.col.f32.tf32.tf32.f32 "
        "{%0,%1,%2,%3}, {%4,%5,%6,%7}, {%8,%9}, {%0,%1,%2,%3};"
        : "+f"(c[0]), "+f"(c[1]), "+f"(c[2]), "+f"(c[3])
        : "r"(a[0]), "r"(a[1]), "r"(a[2]), "r"(a[3]), "r"(b[0]), "r"(b[1]));
}

// ===========================================================================
// Weight transpose (+optional scale): WT[n][k] = W[k][n] * scale
// ===========================================================================
__global__ void __launch_bounds__(256) transpose_w(
    const float* __restrict__ W, float* __restrict__ WT, float scale)
{
    __shared__ float t[32][33];
    const int bx = blockIdx.x * 32, by = blockIdx.y * 32;
    const int x = threadIdx.x, y4 = threadIdx.y;
#pragma unroll
    for (int i = 0; i < 4; i++) {
        const int row = by + y4 * 4 + i;
        t[y4 * 4 + i][x] = W[(size_t)row * DM + bx + x] * scale;
    }
    __syncthreads();
#pragma unroll
    for (int i = 0; i < 4; i++) {
        const int row = bx + y4 * 4 + i;
        WT[(size_t)row * DM + by + x] = t[x][y4 * 4 + i];
    }
}

// ===========================================================================
// TF32 mma.sync GEMM: C[4096,1024] = A[4096,1024] @ BT^T + bias*bscale
//   A row-major [M,K]. BT row-major [N,K] (== B column-major -> row.col mma).
//   Block tile 128x128, 8 warps (2m x 4n), warp tile 64x32.
//   K-chunks of 32, double-buffered cp.async.
//   mode 0: output remapped to [B,H,S,dh]; mode 1: row-major [M,N].
// ===========================================================================
#define TM_BM 128
#define TM_BN 128
#define TM_BK 32
#define TM_STR 36                               // smem row stride in floats
#define TM_TILEF (128 * TM_STR)                 // floats per tile buffer
#define TM_SMEM (4 * TM_TILEF * 4)              // bytes: A0,B0,A1,B1

__device__ __forceinline__ void tm_load_tile(
    const float* __restrict__ G,                // global base: row-major, K-major rows
    uint32_t sbase, int tid)                    // 128 rows x 32 floats
{
#pragma unroll
    for (int i = 0; i < 4; i++) {
        const int idx = tid + (i << 8);         // 0..1023
        const int r = idx >> 3, seg = idx & 7;
        cp16(sbase + (uint32_t)(r * (TM_STR * 4) + seg * 16),
             G + (size_t)r * DM + seg * 4);
    }
}

__global__ void __launch_bounds__(256) gemm_tf32mma(
    const float* __restrict__ A, const float* __restrict__ BT,
    const float* __restrict__ bias, float* __restrict__ C,
    int mode, float bscale)
{
    extern __shared__ float sm[];
    float* bufA[2] = { sm,                sm + 2 * TM_TILEF };
    float* bufB[2] = { sm + TM_TILEF,     sm + 3 * TM_TILEF };
    const uint32_t smem0 = (uint32_t)__cvta_generic_to_shared(sm);

    const int tid  = threadIdx.x;
    const int wid  = tid >> 5, lane = tid & 31;
    const int wm   = wid >> 2;                   // 0..1
    const int wn   = wid & 3;                    // 0..3
    const int g    = lane >> 2;                  // 0..7
    const int kq   = lane & 3;                   // 0..3

    const int m0 = blockIdx.y * TM_BM;
    const int n0 = blockIdx.x * TM_BN;

    const float* Ag = A  + (size_t)m0 * DM;
    const float* Bg = BT + (size_t)n0 * DM;

    float c[4][4][4];
#pragma unroll
    for (int mt = 0; mt < 4; mt++)
#pragma unroll
        for (int nt = 0; nt < 4; nt++)
#pragma unroll
            for (int i = 0; i < 4; i++) c[mt][nt][i] = 0.f;

    // Prefetch chunk 0
    tm_load_tile(Ag, smem0, tid);
    tm_load_tile(Bg, smem0 + TM_TILEF * 4, tid);
    CP_COMMIT();

    const int NCH = DM / TM_BK;                  // 32
    for (int kc = 0; kc < NCH; kc++) {
        if (kc + 1 < NCH) {
            const uint32_t sb = smem0 + (uint32_t)(((kc + 1) & 1) ? 2 * TM_TILEF * 4 : 0);
            tm_load_tile(Ag + (kc + 1) * TM_BK, sb, tid);
            tm_load_tile(Bg + (kc + 1) * TM_BK, sb + TM_TILEF * 4, tid);
            CP_COMMIT();
            CP_WAIT(1);
        } else {
            CP_WAIT(0);
        }
        __syncthreads();

        const float* As = bufA[kc & 1];
        const float* Bs = bufB[kc & 1];

#pragma unroll
        for (int ks = 0; ks < 4; ks++) {
            const int k0 = ks * 8;
            uint32_t af[4][4], bf[4][2];
#pragma unroll
            for (int mt = 0; mt < 4; mt++) {
                const int row = wm * 64 + mt * 16 + g;
                af[mt][0] = f2tf32(As[row * TM_STR + k0 + kq]);
                af[mt][1] = f2tf32(As[(row + 8) * TM_STR + k0 + kq]);
                af[mt][2] = f2tf32(As[row * TM_STR + k0 + kq + 4]);
                af[mt][3] = f2tf32(As[(row + 8) * TM_STR + k0 + kq + 4]);
            }
#pragma unroll
            for (int nt = 0; nt < 4; nt++) {
                const int col = wn * 32 + nt * 8 + g;
                bf[nt][0] = f2tf32(Bs[col * TM_STR + k0 + kq]);
                bf[nt][1] = f2tf32(Bs[col * TM_STR + k0 + kq + 4]);
            }
#pragma unroll
            for (int mt = 0; mt < 4; mt++)
#pragma unroll
                for (int nt = 0; nt < 4; nt++)
                    mma_tf32(c[mt][nt], af[mt], bf[nt]);
        }
        __syncthreads();
    }

    // Epilogue: bias + layout
#pragma unroll
    for (int mt = 0; mt < 4; mt++) {
        const int r1 = m0 + wm * 64 + mt * 16 + g;
        const int r2 = r1 + 8;
        const int b1 = r1 >> 11, s1 = r1 & 2047;
        const int b2 = r2 >> 11, s2 = r2 & 2047;
#pragma unroll
        for (int nt = 0; nt < 4; nt++) {
            const int n = n0 + wn * 32 + nt * 8 + 2 * kq;
            const float bx = bias[n] * bscale, by = bias[n + 1] * bscale;
            float2 v1 = { c[mt][nt][0] + bx, c[mt][nt][1] + by };
            float2 v2 = { c[mt][nt][2] + bx, c[mt][nt][3] + by };
            size_t o1, o2;
            if (mode == 0) {
                const int h = n >> 6, d = n & 63;
                o1 = (((size_t)(b1 * NH + h)) * SEQ + s1) * DH + d;
                o2 = (((size_t)(b2 * NH + h)) * SEQ + s2) * DH + d;
            } else {
                o1 = (size_t)r1 * DM + n;
                o2 = (size_t)r2 * DM + n;
            }
            *(float2*)(C + o1) = v1;
            *(float2*)(C + o2) = v2;
        }
    }
}

// ---------------------------------------------------------------------------
// Flash attention, fp32 SIMT. Q/K/V in [B,H,S,dh]. Output in [B,S,H*dh].
// Scale 1/sqrt(dh) pre-folded into Wq/bq. pH dropped (softmax-invariant).
// ---------------------------------------------------------------------------
#define FA_BQ 64
#define FA_BK 64
#define FA_STR 68

__global__ void __launch_bounds__(256) flash_attn(
    const float* __restrict__ Q, const float* __restrict__ K,
    const float* __restrict__ V, float* __restrict__ Out)
{
    extern __shared__ float smf[];
    float* Qt = smf;
    float* Kt = smf + 64 * FA_STR;
    float* Vs = smf + 2 * 64 * FA_STR;
    float* Pt = smf + 3 * 64 * FA_STR;

    const int tid = threadIdx.x;
    const int ty = tid >> 4, tx = tid & 15;
    const int r0 = ty * 4;
    const int c0 = tx * 4;

    const int q0 = blockIdx.x * FA_BQ;
    const int bh = blockIdx.y;
    const int b = bh >> 4, h = bh & 15;

    const float* Qg = Q + (size_t)bh * SEQ * DH;
    const float* Kg = K + (size_t)bh * SEQ * DH;
    const float* Vg = V + (size_t)bh * SEQ * DH;

    for (int i = tid; i < FA_BQ * (DH / 4); i += 256) {
        const int r = i >> 4;
        const int c = (i & 15) << 2;
        float4 v = *(const float4*)(Qg + (size_t)(q0 + r) * DH + c);
        Qt[(c + 0) * FA_STR + r] = v.x;
        Qt[(c + 1) * FA_STR + r] = v.y;
        Qt[(c + 2) * FA_STR + r] = v.z;
        Qt[(c + 3) * FA_STR + r] = v.w;
    }

    float m[4], l[4], o[4][4];
#pragma unroll
    for (int i = 0; i < 4; i++) {
        m[i] = -INFINITY; l[i] = 0.f;
#pragma unroll
        for (int j = 0; j < 4; j++) o[i][j] = 0.f;
    }

    for (int kt = 0; kt < SEQ / FA_BK; kt++) {
        const int k0 = kt * FA_BK;
        __syncthreads();

        for (int i = tid; i < FA_BK * (DH / 4); i += 256) {
            const int r = i >> 4;
            const int c = (i & 15) << 2;
            float4 kv = *(const float4*)(Kg + (size_t)(k0 + r) * DH + c);
            Kt[(c + 0) * FA_STR + r] = kv.x;
            Kt[(c + 1) * FA_STR + r] = kv.y;
            Kt[(c + 2) * FA_STR + r] = kv.z;
            Kt[(c + 3) * FA_STR + r] = kv.w;
            float4 vv = *(const float4*)(Vg + (size_t)(k0 + r) * DH + c);
            *(float4*)(&Vs[r * FA_STR + c]) = vv;
        }
        __syncthreads();

        float s[4][4];
#pragma unroll
        for (int i = 0; i < 4; i++)
#pragma unroll
            for (int j = 0; j < 4; j++) s[i][j] = 0.f;

#pragma unroll 8
        for (int d = 0; d < DH; d++) {
            float4 qa = *(const float4*)(&Qt[d * FA_STR + r0]);
            float4 kb = *(const float4*)(&Kt[d * FA_STR + c0]);
            const float qr[4] = {qa.x, qa.y, qa.z, qa.w};
            const float kc[4] = {kb.x, kb.y, kb.z, kb.w};
#pragma unroll
            for (int i = 0; i < 4; i++)
#pragma unroll
                for (int j = 0; j < 4; j++)
                    s[i][j] += qr[i] * kc[j];
        }

#pragma unroll
        for (int rr = 0; rr < 4; rr++) {
            float mt = fmaxf(fmaxf(s[rr][0], s[rr][1]), fmaxf(s[rr][2], s[rr][3]));
#pragma unroll
            for (int off = 8; off >= 1; off >>= 1)
                mt = fmaxf(mt, __shfl_xor_sync(0xffffffffu, mt, off, 16));
            const float mn = fmaxf(m[rr], mt);
            const float corr = __expf(m[rr] - mn);
            float ls = 0.f;
#pragma unroll
            for (int cc = 0; cc < 4; cc++) {
                const float p = __expf(s[rr][cc] - mn);
                s[rr][cc] = p;
                ls += p;
            }
#pragma unroll
            for (int off = 8; off >= 1; off >>= 1)
                ls += __shfl_xor_sync(0xffffffffu, ls, off, 16);
            l[rr] = l[rr] * corr + ls;
            m[rr] = mn;
#pragma unroll
            for (int j = 0; j < 4; j++) o[rr][j] *= corr;
        }

#pragma unroll
        for (int cc = 0; cc < 4; cc++)
#pragma unroll
            for (int rr = 0; rr < 4; rr++)
                Pt[(c0 + cc) * FA_STR + (r0 + rr)] = s[rr][cc];
        __syncthreads();

#pragma unroll 8
        for (int cidx = 0; cidx < FA_BK; cidx++) {
            float4 pv = *(const float4*)(&Pt[cidx * FA_STR + r0]);
            float4 vv = *(const float4*)(&Vs[cidx * FA_STR + c0]);
            const float pr[4] = {pv.x, pv.y, pv.z, pv.w};
            const float vc[4] = {vv.x, vv.y, vv.z, vv.w};
#pragma unroll
            for (int i = 0; i < 4; i++)
#pragma unroll
                for (int j = 0; j < 4; j++)
                    o[i][j] += pr[i] * vc[j];
        }
    }

#pragma unroll
    for (int rr = 0; rr < 4; rr++) {
        const float inv = 1.f / l[rr];
        const int row = q0 + r0 + rr;
        float4 out;
        out.x = o[rr][0] * inv;
        out.y = o[rr][1] * inv;
        out.z = o[rr][2] * inv;
        out.w = o[rr][3] * inv;
        *(float4*)(&Out[((size_t)b * SEQ + row) * DM + h * DH + c0]) = out;
    }
}

// ---------------------------------------------------------------------------
// Launch
// ---------------------------------------------------------------------------
extern "C" void kernel_launch(void* const* d_in, const int* in_sizes, int n_in,
                              void* d_out, int out_size)
{
    const float* x  = (const float*)d_in[0];
    // d_in[1] = pH : constant along softmax axis -> provably no effect
    const float* Wq = (const float*)d_in[2];
    const float* bq = (const float*)d_in[3];
    const float* Wk = (const float*)d_in[4];
    const float* bk = (const float*)d_in[5];
    const float* Wv = (const float*)d_in[6];
    const float* bv = (const float*)d_in[7];
    const float* Wo = (const float*)d_in[8];
    const float* bo = (const float*)d_in[9];
    float* out = (float*)d_out;

    float *qp, *kp, *vp, *ap, *wt;
    cudaGetSymbolAddress((void**)&qp, g_Q);
    cudaGetSymbolAddress((void**)&kp, g_K);
    cudaGetSymbolAddress((void**)&vp, g_V);
    cudaGetSymbolAddress((void**)&ap, g_ATT);
    cudaGetSymbolAddress((void**)&wt, g_WT);
    float* wtq = wt;
    float* wtk = wt + (size_t)DM * DM;
    float* wtv = wt + 2 * (size_t)DM * DM;
    float* wto = wt + 3 * (size_t)DM * DM;

    const int smem_fa = 4 * 64 * FA_STR * sizeof(float);
    cudaFuncSetAttribute(flash_attn, cudaFuncAttributeMaxDynamicSharedMemorySize, smem_fa);
    cudaFuncSetAttribute(gemm_tf32mma, cudaFuncAttributeMaxDynamicSharedMemorySize, TM_SMEM);

    const float qscale = 0.125f;  // 1/sqrt(64), folded into Wq/bq

    dim3 tb(32, 8), tg(32, 32);
    transpose_w<<<tg, tb>>>(Wq, wtq, qscale);
    transpose_w<<<tg, tb>>>(Wk, wtk, 1.0f);
    transpose_w<<<tg, tb>>>(Wv, wtv, 1.0f);
    transpose_w<<<tg, tb>>>(Wo, wto, 1.0f);

    dim3 gg(DM / TM_BN, MROWS / TM_BM);   // (8, 32)
    gemm_tf32mma<<<gg, 256, TM_SMEM>>>(x, wtq, bq, qp, 0, qscale);
    gemm_tf32mma<<<gg, 256, TM_SMEM>>>(x, wtk, bk, kp, 0, 1.0f);
    gemm_tf32mma<<<gg, 256, TM_SMEM>>>(x, wtv, bv, vp, 0, 1.0f);

    dim3 ga(SEQ / FA_BQ, BATCH * NH);     // (32, 32)
    flash_attn<<<ga, 256, smem_fa>>>(qp, kp, vp, ap);

    gemm_tf32mma<<<gg, 256, TM_SMEM>>>(ap, wto, bo, out, 1, 1.0f);
}

// round 4
// speedup vs baseline: 3.2337x; 1.9488x over previous
#include <cuda_runtime.h>
#include <math.h>
#include <stdint.h>

// Problem constants (fixed shapes)
#define BATCH 2
#define SEQ   2048
#define DM    1024
#define NH    16
#define DH    64
#define MROWS (BATCH*SEQ)          // 4096
#define QKV_OFF (BATCH*NH*SEQ*DH)  // 4194304

// Scratch (device globals; allocation-free)
__device__ float g_QKV[3*QKV_OFF]; // Q | K | V in [B,H,S,dh]
__device__ float g_ATT[MROWS*DM];
__device__ float g_WT[3*DM*DM];    // Wq^T | Wk^T | Wv^T (K-major [N,K])
__device__ float g_WTO[DM*DM];     // Wo^T
__device__ float g_BIAS[3*DM];     // packed bq*s | bk | bv

// ===========================================================================
// Helpers (baseline sm_80+ PTX only — no 'a'-gated features)
// ===========================================================================
__device__ __forceinline__ void cp16(uint32_t s, const void* g) {
    asm volatile("cp.async.cg.shared.global [%0], [%1], 16;" :: "r"(s), "l"(g));
}
#define CP_COMMIT() asm volatile("cp.async.commit_group;" ::: "memory")
#define CP_WAIT(N)  asm volatile("cp.async.wait_group %0;" :: "n"(N) : "memory")

__device__ __forceinline__ uint32_t f2tf32(float f) {
    uint32_t r;
    asm("cvt.rna.tf32.f32 %0, %1;" : "=r"(r) : "f"(f));
    return r;
}

__device__ __forceinline__ void mma_tf32(float c[4], const uint32_t a[4], const uint32_t b[2]) {
    asm volatile(
        "mma.sync.aligned.m16n8k8.row.col.f32.tf32.tf32.f32 "
        "{%0,%1,%2,%3}, {%4,%5,%6,%7}, {%8,%9}, {%0,%1,%2,%3};"
        : "+f"(c[0]), "+f"(c[1]), "+f"(c[2]), "+f"(c[3])
        : "r"(a[0]), "r"(a[1]), "r"(a[2]), "r"(a[3]), "r"(b[0]), "r"(b[1]));
}

// ===========================================================================
// Weight transpose (+optional scale): WT[n][k] = W[k][n] * scale
// ===========================================================================
__global__ void __launch_bounds__(256) transpose_w(
    const float* __restrict__ W, float* __restrict__ WT, float scale)
{
    __shared__ float t[32][33];
    const int bx = blockIdx.x * 32, by = blockIdx.y * 32;
    const int x = threadIdx.x, y4 = threadIdx.y;
#pragma unroll
    for (int i = 0; i < 4; i++) {
        const int row = by + y4 * 4 + i;
        t[y4 * 4 + i][x] = W[(size_t)row * DM + bx + x] * scale;
    }
    __syncthreads();
#pragma unroll
    for (int i = 0; i < 4; i++) {
        const int row = bx + y4 * 4 + i;
        WT[(size_t)row * DM + by + x] = t[x][y4 * 4 + i];
    }
}

__global__ void __launch_bounds__(256) pack_bias(
    const float* __restrict__ bq, const float* __restrict__ bk,
    const float* __restrict__ bv, float* __restrict__ dst)
{
    const int i = blockIdx.x * 256 + threadIdx.x;   // 0..3071
    float v;
    if (i < 1024)       v = bq[i] * 0.125f;
    else if (i < 2048)  v = bk[i - 1024];
    else                v = bv[i - 2048];
    dst[i] = v;
}

// ===========================================================================
// TF32 mma.sync GEMM: C[4096, N] = A[4096,1024] @ BT^T + bias
//   Block tile 128x128, 8 warps (2m x 4n), warp tile 64x32.
//   mode 0: QKV merged (N=3072): output remapped to 3 x [B,H,S,dh],
//           values pre-rounded to TF32 (cvt.rna) for the attention kernel.
//   mode 1: row-major [M,1024].
// ===========================================================================
#define TM_STR 36
#define TM_TILEF (128 * TM_STR)
#define TM_SMEM (4 * TM_TILEF * 4)

__device__ __forceinline__ void tm_load_tile(
    const float* __restrict__ G, uint32_t sbase, int tid)
{
#pragma unroll
    for (int i = 0; i < 4; i++) {
        const int idx = tid + (i << 8);
        const int r = idx >> 3, seg = idx & 7;
        cp16(sbase + (uint32_t)(r * (TM_STR * 4) + seg * 16),
             G + (size_t)r * DM + seg * 4);
    }
}

__global__ void __launch_bounds__(256) gemm_tf32mma(
    const float* __restrict__ A, const float* __restrict__ BT,
    const float* __restrict__ bias, float* __restrict__ C, int mode)
{
    extern __shared__ float sm[];
    float* bufA[2] = { sm,            sm + 2 * TM_TILEF };
    float* bufB[2] = { sm + TM_TILEF, sm + 3 * TM_TILEF };
    const uint32_t smem0 = (uint32_t)__cvta_generic_to_shared(sm);

    const int tid  = threadIdx.x;
    const int wid  = tid >> 5, lane = tid & 31;
    const int wm   = wid >> 2;
    const int wn   = wid & 3;
    const int g    = lane >> 2;
    const int kq   = lane & 3;

    const int m0 = blockIdx.y * 128;
    const int n0 = blockIdx.x * 128;

    const float* Ag = A  + (size_t)m0 * DM;
    const float* Bg = BT + (size_t)n0 * DM;

    float c[4][4][4];
#pragma unroll
    for (int mt = 0; mt < 4; mt++)
#pragma unroll
        for (int nt = 0; nt < 4; nt++)
#pragma unroll
            for (int i = 0; i < 4; i++) c[mt][nt][i] = 0.f;

    tm_load_tile(Ag, smem0, tid);
    tm_load_tile(Bg, smem0 + TM_TILEF * 4, tid);
    CP_COMMIT();

    const int NCH = DM / 32;
    for (int kc = 0; kc < NCH; kc++) {
        if (kc + 1 < NCH) {
            const uint32_t sb = smem0 + (uint32_t)(((kc + 1) & 1) ? 2 * TM_TILEF * 4 : 0);
            tm_load_tile(Ag + (kc + 1) * 32, sb, tid);
            tm_load_tile(Bg + (kc + 1) * 32, sb + TM_TILEF * 4, tid);
            CP_COMMIT();
            CP_WAIT(1);
        } else {
            CP_WAIT(0);
        }
        __syncthreads();

        const float* As = bufA[kc & 1];
        const float* Bs = bufB[kc & 1];

#pragma unroll
        for (int ks = 0; ks < 4; ks++) {
            const int k0 = ks * 8;
            uint32_t af[4][4], bf[4][2];
#pragma unroll
            for (int mt = 0; mt < 4; mt++) {
                const int row = wm * 64 + mt * 16 + g;
                af[mt][0] = f2tf32(As[row * TM_STR + k0 + kq]);
                af[mt][1] = f2tf32(As[(row + 8) * TM_STR + k0 + kq]);
                af[mt][2] = f2tf32(As[row * TM_STR + k0 + kq + 4]);
                af[mt][3] = f2tf32(As[(row + 8) * TM_STR + k0 + kq + 4]);
            }
#pragma unroll
            for (int nt = 0; nt < 4; nt++) {
                const int col = wn * 32 + nt * 8 + g;
                bf[nt][0] = f2tf32(Bs[col * TM_STR + k0 + kq]);
                bf[nt][1] = f2tf32(Bs[col * TM_STR + k0 + kq + 4]);
            }
#pragma unroll
            for (int mt = 0; mt < 4; mt++)
#pragma unroll
                for (int nt = 0; nt < 4; nt++)
                    mma_tf32(c[mt][nt], af[mt], bf[nt]);
        }
        __syncthreads();
    }

    // Epilogue
#pragma unroll
    for (int mt = 0; mt < 4; mt++) {
        const int r1 = m0 + wm * 64 + mt * 16 + g;
        const int r2 = r1 + 8;
        const int b1 = r1 >> 11, s1 = r1 & 2047;
        const int b2 = r2 >> 11, s2 = r2 & 2047;
#pragma unroll
        for (int nt = 0; nt < 4; nt++) {
            const int n = n0 + wn * 32 + nt * 8 + 2 * kq;
            const float bx = bias[n], by = bias[n + 1];
            float2 v1 = { c[mt][nt][0] + bx, c[mt][nt][1] + by };
            float2 v2 = { c[mt][nt][2] + bx, c[mt][nt][3] + by };
            if (mode == 0) {
                // Pre-round to TF32 so the attention kernel can feed raw bits.
                v1.x = __uint_as_float(f2tf32(v1.x));
                v1.y = __uint_as_float(f2tf32(v1.y));
                v2.x = __uint_as_float(f2tf32(v2.x));
                v2.y = __uint_as_float(f2tf32(v2.y));
                const int which = n >> 10;
                const int nn = n & 1023;
                const int h = nn >> 6, d = nn & 63;
                const size_t base = (size_t)which * QKV_OFF;
                *(float2*)(C + base + (((size_t)(b1 * NH + h)) * SEQ + s1) * DH + d) = v1;
                *(float2*)(C + base + (((size_t)(b2 * NH + h)) * SEQ + s2) * DH + d) = v2;
            } else {
                *(float2*)(C + (size_t)r1 * DM + n) = v1;
                *(float2*)(C + (size_t)r2 * DM + n) = v2;
            }
        }
    }
}

// ===========================================================================
// Flash attention, TF32 mma.sync. Q/K/V in [B,H,S,dh] (TF32-pre-rounded).
// Output [B,S,H*dh] fp32. BQ=128, BK=128, 8 warps x m16.
// P reused as A-operand via register shuffles (no smem round-trip).
// ===========================================================================
#define FA_STR 76
#define FA_TILEF (128 * FA_STR)
#define FA_SMEM (5 * FA_TILEF * 4)   // Q + 2xK + 2xV = 194560 bytes

__device__ __forceinline__ void fa_load_tile(
    const float* __restrict__ G, uint32_t sb, int tid)
{
#pragma unroll
    for (int i = 0; i < 8; i++) {
        const int idx = tid + (i << 8);
        const int r = idx >> 4, s = idx & 15;
        cp16(sb + (uint32_t)(r * (FA_STR * 4) + s * 16), G + r * DH + s * 4);
    }
}

__global__ void __launch_bounds__(256) fa_mma(
    const float* __restrict__ Q, const float* __restrict__ K,
    const float* __restrict__ V, float* __restrict__ Out)
{
    extern __shared__ float sm[];
    float* Qs = sm;
    float* Ksb[2] = { sm + FA_TILEF,     sm + 2 * FA_TILEF };
    float* Vsb[2] = { sm + 3 * FA_TILEF, sm + 4 * FA_TILEF };
    const uint32_t smem0 = (uint32_t)__cvta_generic_to_shared(sm);

    const int tid = threadIdx.x;
    const int wid = tid >> 5, lane = tid & 31;
    const int g = lane >> 2, kq = lane & 3;

    const int q0 = blockIdx.x * 128;
    const int bh = blockIdx.y;
    const int b = bh >> 4, h = bh & 15;

    const float* Qg = Q + (size_t)bh * SEQ * DH + (size_t)q0 * DH;
    const float* Kg = K + (size_t)bh * SEQ * DH;
    const float* Vg = V + (size_t)bh * SEQ * DH;

    // Prefetch: Q (group0), K0+V0 (group1)
    fa_load_tile(Qg, smem0, tid);
    CP_COMMIT();
    fa_load_tile(Kg, smem0 + FA_TILEF * 4, tid);
    fa_load_tile(Vg, smem0 + 3 * FA_TILEF * 4, tid);
    CP_COMMIT();

    float m0 = -INFINITY, m1 = -INFINITY, l0 = 0.f, l1 = 0.f;
    float co[8][4];
#pragma unroll
    for (int nt = 0; nt < 8; nt++)
#pragma unroll
        for (int i = 0; i < 4; i++) co[nt][i] = 0.f;

    const int qrow = wid * 16 + g;
    const int srcA = (lane & ~3) | (kq >> 1);
    const int srcB = srcA + 2;
    const int psel = kq & 1;

    for (int t = 0; t < SEQ / 128; t++) {
        __syncthreads();   // all warps done reading the buffer we overwrite next
        if (t + 1 < SEQ / 128) {
            const uint32_t koff = ((t + 1) & 1) ? 2u : 1u;
            fa_load_tile(Kg + (size_t)(t + 1) * 128 * DH,
                         smem0 + koff * FA_TILEF * 4, tid);
            fa_load_tile(Vg + (size_t)(t + 1) * 128 * DH,
                         smem0 + (koff + 2) * FA_TILEF * 4, tid);
            CP_COMMIT();
            CP_WAIT(1);
        } else {
            CP_WAIT(0);
        }
        __syncthreads();

        const float* Ks = Ksb[t & 1];
        const float* Vs = Vsb[t & 1];

        // ---- scores: S[16 x 128] = Q_tile @ K_tile^T (values pre-scaled) ----
        float cs[16][4];
#pragma unroll
        for (int nt = 0; nt < 16; nt++)
#pragma unroll
            for (int i = 0; i < 4; i++) cs[nt][i] = 0.f;

#pragma unroll
        for (int k8 = 0; k8 < 8; k8++) {
            const int ka = 8 * k8 + kq;
            uint32_t a[4];
            a[0] = __float_as_uint(Qs[qrow * FA_STR + ka]);
            a[1] = __float_as_uint(Qs[(qrow + 8) * FA_STR + ka]);
            a[2] = __float_as_uint(Qs[qrow * FA_STR + ka + 4]);
            a[3] = __float_as_uint(Qs[(qrow + 8) * FA_STR + ka + 4]);
#pragma unroll
            for (int nt = 0; nt < 16; nt++) {
                uint32_t bfr[2];
                bfr[0] = __float_as_uint(Ks[(8 * nt + g) * FA_STR + ka]);
                bfr[1] = __float_as_uint(Ks[(8 * nt + g) * FA_STR + ka + 4]);
                mma_tf32(cs[nt], a, bfr);
            }
        }

        // ---- online softmax (rows g and g+8), all in registers ----
        float tm0 = -INFINITY, tm1 = -INFINITY;
#pragma unroll
        for (int nt = 0; nt < 16; nt++) {
            tm0 = fmaxf(tm0, fmaxf(cs[nt][0], cs[nt][1]));
            tm1 = fmaxf(tm1, fmaxf(cs[nt][2], cs[nt][3]));
        }
        tm0 = fmaxf(tm0, __shfl_xor_sync(0xffffffffu, tm0, 1));
        tm0 = fmaxf(tm0, __shfl_xor_sync(0xffffffffu, tm0, 2));
        tm1 = fmaxf(tm1, __shfl_xor_sync(0xffffffffu, tm1, 1));
        tm1 = fmaxf(tm1, __shfl_xor_sync(0xffffffffu, tm1, 2));

        const float mn0 = fmaxf(m0, tm0), mn1 = fmaxf(m1, tm1);
        const float corr0 = __expf(m0 - mn0), corr1 = __expf(m1 - mn1);
        m0 = mn0; m1 = mn1;

        float s0 = 0.f, s1 = 0.f;
#pragma unroll
        for (int nt = 0; nt < 16; nt++) {
            float p0 = __expf(cs[nt][0] - mn0);
            float p1 = __expf(cs[nt][1] - mn0);
            float p2 = __expf(cs[nt][2] - mn1);
            float p3 = __expf(cs[nt][3] - mn1);
            s0 += p0 + p1; s1 += p2 + p3;
            // convert P to tf32 (rna) for the PV mma; keep bits in cs
            cs[nt][0] = __uint_as_float(f2tf32(p0));
            cs[nt][1] = __uint_as_float(f2tf32(p1));
            cs[nt][2] = __uint_as_float(f2tf32(p2));
            cs[nt][3] = __uint_as_float(f2tf32(p3));
        }
        s0 += __shfl_xor_sync(0xffffffffu, s0, 1);
        s0 += __shfl_xor_sync(0xffffffffu, s0, 2);
        s1 += __shfl_xor_sync(0xffffffffu, s1, 1);
        s1 += __shfl_xor_sync(0xffffffffu, s1, 2);
        l0 = l0 * corr0 + s0;
        l1 = l1 * corr1 + s1;

#pragma unroll
        for (int nt = 0; nt < 8; nt++) {
            co[nt][0] *= corr0; co[nt][1] *= corr0;
            co[nt][2] *= corr1; co[nt][3] *= corr1;
        }

        // ---- PV: out[16 x 64] += P[16 x 128] @ V[128 x 64] ----
#pragma unroll
        for (int j = 0; j < 16; j++) {
            const uint32_t x0 = __shfl_sync(0xffffffffu, __float_as_uint(cs[j][0]), srcA);
            const uint32_t x1 = __shfl_sync(0xffffffffu, __float_as_uint(cs[j][1]), srcA);
            const uint32_t x2 = __shfl_sync(0xffffffffu, __float_as_uint(cs[j][2]), srcA);
            const uint32_t x3 = __shfl_sync(0xffffffffu, __float_as_uint(cs[j][3]), srcA);
            const uint32_t y0 = __shfl_sync(0xffffffffu, __float_as_uint(cs[j][0]), srcB);
            const uint32_t y1 = __shfl_sync(0xffffffffu, __float_as_uint(cs[j][1]), srcB);
            const uint32_t y2 = __shfl_sync(0xffffffffu, __float_as_uint(cs[j][2]), srcB);
            const uint32_t y3 = __shfl_sync(0xffffffffu, __float_as_uint(cs[j][3]), srcB);
            uint32_t a[4];
            a[0] = psel ? x1 : x0;   // P[g   ][8j+kq]
            a[1] = psel ? x3 : x2;   // P[g+8 ][8j+kq]
            a[2] = psel ? y1 : y0;   // P[g   ][8j+kq+4]
            a[3] = psel ? y3 : y2;   // P[g+8 ][8j+kq+4]
            const int kr = 8 * j + kq;
#pragma unroll
            for (int nt = 0; nt < 8; nt++) {
                uint32_t bfr[2];
                bfr[0] = __float_as_uint(Vs[kr * FA_STR + 8 * nt + g]);
                bfr[1] = __float_as_uint(Vs[(kr + 4) * FA_STR + 8 * nt + g]);
                mma_tf32(co[nt], a, bfr);
            }
        }
    }

    // ---- epilogue: normalize, write [B, S, H*dh] ----
    const float inv0 = 1.f / l0, inv1 = 1.f / l1;
    float* Og = Out + ((size_t)b * SEQ + (q0 + qrow)) * DM + h * DH;
#pragma unroll
    for (int nt = 0; nt < 8; nt++) {
        float2 v0 = { co[nt][0] * inv0, co[nt][1] * inv0 };
        float2 v1 = { co[nt][2] * inv1, co[nt][3] * inv1 };
        *(float2*)(Og + 8 * nt + 2 * kq) = v0;
        *(float2*)(Og + (size_t)8 * DM + 8 * nt + 2 * kq) = v1;
    }
}

// ---------------------------------------------------------------------------
// Launch
// ---------------------------------------------------------------------------
extern "C" void kernel_launch(void* const* d_in, const int* in_sizes, int n_in,
                              void* d_out, int out_size)
{
    const float* x  = (const float*)d_in[0];
    // d_in[1] = pH : constant along softmax axis -> provably no effect
    const float* Wq = (const float*)d_in[2];
    const float* bq = (const float*)d_in[3];
    const float* Wk = (const float*)d_in[4];
    const float* bk = (const float*)d_in[5];
    const float* Wv = (const float*)d_in[6];
    const float* bv = (const float*)d_in[7];
    const float* Wo = (const float*)d_in[8];
    const float* bo = (const float*)d_in[9];
    float* out = (float*)d_out;

    float *qkv, *ap, *wt, *wto, *bias;
    cudaGetSymbolAddress((void**)&qkv,  g_QKV);
    cudaGetSymbolAddress((void**)&ap,   g_ATT);
    cudaGetSymbolAddress((void**)&wt,   g_WT);
    cudaGetSymbolAddress((void**)&wto,  g_WTO);
    cudaGetSymbolAddress((void**)&bias, g_BIAS);

    cudaFuncSetAttribute(gemm_tf32mma, cudaFuncAttributeMaxDynamicSharedMemorySize, TM_SMEM);
    cudaFuncSetAttribute(fa_mma, cudaFuncAttributeMaxDynamicSharedMemorySize, FA_SMEM);

    const float qscale = 0.125f;  // 1/sqrt(64), folded into Wq/bq

    dim3 tb(32, 8), tg(32, 32);
    transpose_w<<<tg, tb>>>(Wq, wt, qscale);
    transpose_w<<<tg, tb>>>(Wk, wt + (size_t)DM * DM, 1.0f);
    transpose_w<<<tg, tb>>>(Wv, wt + 2 * (size_t)DM * DM, 1.0f);
    transpose_w<<<tg, tb>>>(Wo, wto, 1.0f);
    pack_bias<<<12, 256>>>(bq, bk, bv, bias);

    // Merged QKV projection: N = 3072
    dim3 gq(3 * DM / 128, MROWS / 128);   // (24, 32)
    gemm_tf32mma<<<gq, 256, TM_SMEM>>>(x, wt, bias, qkv, 0);

    // Attention
    dim3 ga(SEQ / 128, BATCH * NH);       // (16, 32)
    fa_mma<<<ga, 256, FA_SMEM>>>(qkv, qkv + QKV_OFF, qkv + 2 * QKV_OFF, ap);

    // Output projection
    dim3 go(DM / 128, MROWS / 128);       // (8, 32)
    gemm_tf32mma<<<go, 256, TM_SMEM>>>(ap, wto, bo, out, 1);
}

// round 5
// speedup vs baseline: 7.8018x; 2.4126x over previous
#include <cuda_runtime.h>
#include <cuda_fp16.h>
#include <math.h>
#include <stdint.h>

// Problem constants (fixed shapes)
#define BATCH 2
#define SEQ   2048
#define DM    1024
#define NH    16
#define DH    64
#define MROWS (BATCH*SEQ)          // 4096
#define QKV_OFF (BATCH*NH*SEQ*DH)  // 4194304

// Scratch (device globals; allocation-free)
__device__ __half g_X16[MROWS*DM];   // x converted to fp16
__device__ __half g_QKV[3*QKV_OFF];  // Q | K | V in [B,H,S,dh], fp16
__device__ __half g_ATT[MROWS*DM];   // attention output, fp16
__device__ __half g_WT[3*DM*DM];     // Wq^T | Wk^T | Wv^T (K-major [N,K]) fp16
__device__ __half g_WTO[DM*DM];      // Wo^T fp16
__device__ float  g_BIAS[3*DM];      // packed bq*s | bk | bv (fp32)

// ===========================================================================
// Helpers (baseline sm_80 PTX only — no 'a'-gated features)
// ===========================================================================
__device__ __forceinline__ void cp16(uint32_t s, const void* g) {
    asm volatile("cp.async.cg.shared.global [%0], [%1], 16;" :: "r"(s), "l"(g));
}
#define CP_COMMIT() asm volatile("cp.async.commit_group;" ::: "memory")
#define CP_WAIT(N)  asm volatile("cp.async.wait_group %0;" :: "n"(N) : "memory")

__device__ __forceinline__ void ldm_x4(uint32_t r[4], uint32_t a) {
    asm volatile("ldmatrix.sync.aligned.m8n8.x4.shared.b16 {%0,%1,%2,%3}, [%4];"
                 : "=r"(r[0]), "=r"(r[1]), "=r"(r[2]), "=r"(r[3]) : "r"(a));
}
__device__ __forceinline__ void ldm_x4t(uint32_t r[4], uint32_t a) {
    asm volatile("ldmatrix.sync.aligned.m8n8.x4.trans.shared.b16 {%0,%1,%2,%3}, [%4];"
                 : "=r"(r[0]), "=r"(r[1]), "=r"(r[2]), "=r"(r[3]) : "r"(a));
}

__device__ __forceinline__ void mma_f16(float c[4],
    uint32_t a0, uint32_t a1, uint32_t a2, uint32_t a3,
    uint32_t b0, uint32_t b1)
{
    asm volatile(
        "mma.sync.aligned.m16n8k16.row.col.f32.f16.f16.f32 "
        "{%0,%1,%2,%3}, {%4,%5,%6,%7}, {%8,%9}, {%0,%1,%2,%3};"
        : "+f"(c[0]), "+f"(c[1]), "+f"(c[2]), "+f"(c[3])
        : "r"(a0), "r"(a1), "r"(a2), "r"(a3), "r"(b0), "r"(b1));
}

__device__ __forceinline__ uint32_t pack2(float a, float b) {
    __half2 h = __floats2half2_rn(a, b);
    return *(uint32_t*)&h;
}

// ===========================================================================
// Prep kernels
// ===========================================================================
__global__ void __launch_bounds__(256) f2h(const float* __restrict__ in,
                                           __half* __restrict__ out)
{
    const int i = (blockIdx.x * 256 + threadIdx.x) * 4;
    float4 v = *(const float4*)(in + i);
    *(__half2*)(out + i)     = __floats2half2_rn(v.x, v.y);
    *(__half2*)(out + i + 2) = __floats2half2_rn(v.z, v.w);
}

// WT[n][k] = W[k][n] * scale, output fp16
__global__ void __launch_bounds__(256) transpose_w(
    const float* __restrict__ W, __half* __restrict__ WT, float scale)
{
    __shared__ float t[32][33];
    const int bx = blockIdx.x * 32, by = blockIdx.y * 32;
    const int x = threadIdx.x, y4 = threadIdx.y;
#pragma unroll
    for (int i = 0; i < 4; i++) {
        const int row = by + y4 * 4 + i;
        t[y4 * 4 + i][x] = W[(size_t)row * DM + bx + x] * scale;
    }
    __syncthreads();
#pragma unroll
    for (int i = 0; i < 4; i++) {
        const int row = bx + y4 * 4 + i;
        WT[(size_t)row * DM + by + x] = __float2half(t[x][y4 * 4 + i]);
    }
}

__global__ void __launch_bounds__(256) pack_bias(
    const float* __restrict__ bq, const float* __restrict__ bk,
    const float* __restrict__ bv, float* __restrict__ dst)
{
    const int i = blockIdx.x * 256 + threadIdx.x;
    float v;
    if (i < 1024)       v = bq[i] * 0.125f;
    else if (i < 2048)  v = bk[i - 1024];
    else                v = bv[i - 2048];
    dst[i] = v;
}

// ===========================================================================
// FP16 mma GEMM: C[4096, N] = A[4096,1024] @ BT^T + bias
//   A, BT fp16 row-major (K-major rows). Block 128x128, 8 warps (2m x 4n),
//   warp tile 64x32. BK=64, double-buffered cp.async, ldmatrix fragments.
//   mode 0: QKV merged (N=3072): out -> 3 x [B,H,S,dh] fp16.
//   mode 1: out fp32 row-major [M,1024].
// SMEM: rows of 64 halfs padded to 72 (144B, 9x16B -> ldmatrix conflict-free).
// ===========================================================================
#define TM_STRH 72
#define TM_TILEB (128 * TM_STRH * 2)          // 18432 B per tile
#define TM_SMEM (4 * TM_TILEB)                // A0,B0,A1,B1

__device__ __forceinline__ void tile_load_64h(
    const __half* __restrict__ G, int gstride, uint32_t sbase, int tid)
{
#pragma unroll
    for (int i = 0; i < 4; i++) {
        const int idx = tid + (i << 8);       // 0..1023
        const int r = idx >> 3, s = idx & 7;
        cp16(sbase + (uint32_t)(r * 144 + s * 16), G + (size_t)r * gstride + s * 8);
    }
}

__global__ void __launch_bounds__(256) gemm_f16(
    const __half* __restrict__ A, const __half* __restrict__ BT,
    const float* __restrict__ bias, void* __restrict__ Cout, int mode)
{
    extern __shared__ __align__(16) char smraw[];
    const uint32_t smem0 = (uint32_t)__cvta_generic_to_shared(smraw);
    // buffers: [A0][B0][A1][B1]
    const int tid  = threadIdx.x;
    const int wid  = tid >> 5, lane = tid & 31;
    const int wm   = wid >> 2, wn = wid & 3;
    const int g    = lane >> 2, kq = lane & 3;
    const int lrow = lane & 15;
    const int lcol = (lane >> 4) * 16;        // byte offset of k-half select

    const int m0 = blockIdx.y * 128;
    const int n0 = blockIdx.x * 128;

    const __half* Ag = A  + (size_t)m0 * DM;
    const __half* Bg = BT + (size_t)n0 * DM;

    float c[4][4][4];
#pragma unroll
    for (int mt = 0; mt < 4; mt++)
#pragma unroll
        for (int nt = 0; nt < 4; nt++)
#pragma unroll
            for (int i = 0; i < 4; i++) c[mt][nt][i] = 0.f;

    tile_load_64h(Ag, DM, smem0, tid);
    tile_load_64h(Bg, DM, smem0 + TM_TILEB, tid);
    CP_COMMIT();

    const int NCH = DM / 64;                   // 16
    for (int kc = 0; kc < NCH; kc++) {
        if (kc + 1 < NCH) {
            const uint32_t sb = smem0 + (((kc + 1) & 1) ? 2u * TM_TILEB : 0u);
            tile_load_64h(Ag + (kc + 1) * 64, DM, sb, tid);
            tile_load_64h(Bg + (kc + 1) * 64, DM, sb + TM_TILEB, tid);
            CP_COMMIT();
            CP_WAIT(1);
        } else {
            CP_WAIT(0);
        }
        __syncthreads();

        const uint32_t sA = smem0 + ((kc & 1) ? 2u * TM_TILEB : 0u);
        const uint32_t sB = sA + TM_TILEB;
        const uint32_t aBase = sA + (uint32_t)((wm * 64 + lrow) * 144) + lcol;
        const uint32_t bBase = sB + (uint32_t)((wn * 32 + lrow) * 144) + lcol;

#pragma unroll
        for (int ks = 0; ks < 4; ks++) {       // 4 x k16
            uint32_t af[4][4], bf[2][4];
#pragma unroll
            for (int mt = 0; mt < 4; mt++)
                ldm_x4(af[mt], aBase + (uint32_t)(mt * 16 * 144) + ks * 32);
#pragma unroll
            for (int np = 0; np < 2; np++)
                ldm_x4(bf[np], bBase + (uint32_t)(np * 16 * 144) + ks * 32);
#pragma unroll
            for (int mt = 0; mt < 4; mt++) {
#pragma unroll
                for (int np = 0; np < 2; np++) {
                    mma_f16(c[mt][2*np],   af[mt][0], af[mt][1], af[mt][2], af[mt][3],
                            bf[np][0], bf[np][2]);
                    mma_f16(c[mt][2*np+1], af[mt][0], af[mt][1], af[mt][2], af[mt][3],
                            bf[np][1], bf[np][3]);
                }
            }
        }
        __syncthreads();
    }

    // Epilogue
#pragma unroll
    for (int mt = 0; mt < 4; mt++) {
        const int r1 = m0 + wm * 64 + mt * 16 + g;
        const int r2 = r1 + 8;
        const int b1 = r1 >> 11, s1 = r1 & 2047;
        const int b2 = r2 >> 11, s2 = r2 & 2047;
#pragma unroll
        for (int nt = 0; nt < 4; nt++) {
            const int n = n0 + wn * 32 + nt * 8 + 2 * kq;
            const float bx = bias[n], by = bias[n + 1];
            const float v10 = c[mt][nt][0] + bx, v11 = c[mt][nt][1] + by;
            const float v20 = c[mt][nt][2] + bx, v21 = c[mt][nt][3] + by;
            if (mode == 0) {
                __half* C = (__half*)Cout;
                const int which = n >> 10;
                const int nn = n & 1023;
                const int h = nn >> 6, d = nn & 63;
                const size_t base = (size_t)which * QKV_OFF;
                *(__half2*)(C + base + (((size_t)(b1 * NH + h)) * SEQ + s1) * DH + d) =
                    __floats2half2_rn(v10, v11);
                *(__half2*)(C + base + (((size_t)(b2 * NH + h)) * SEQ + s2) * DH + d) =
                    __floats2half2_rn(v20, v21);
            } else {
                float* C = (float*)Cout;
                *(float2*)(C + (size_t)r1 * DM + n) = make_float2(v10, v11);
                *(float2*)(C + (size_t)r2 * DM + n) = make_float2(v20, v21);
            }
        }
    }
}

// ===========================================================================
// Flash attention, FP16 mma. Q/K/V fp16 [B,H,S,dh]. Output fp16 [B,S,H*dh].
// BQ=128, BK=128, 8 warps x m16. P reused as A-fragment via plain repack.
// ===========================================================================
#define FA_TILEB (128 * TM_STRH * 2)          // 18432 B
#define FA_SMEM (5 * FA_TILEB)                // Q + 2K + 2V = 92160 B

__global__ void __launch_bounds__(256) fa_mma(
    const __half* __restrict__ Q, const __half* __restrict__ K,
    const __half* __restrict__ V, __half* __restrict__ Out)
{
    extern __shared__ __align__(16) char smraw[];
    const uint32_t smem0 = (uint32_t)__cvta_generic_to_shared(smraw);
    const uint32_t smQ = smem0;
    // K buffers at 1,2; V buffers at 3,4

    const int tid = threadIdx.x;
    const int wid = tid >> 5, lane = tid & 31;
    const int g = lane >> 2, kq = lane & 3;
    const int lrow = lane & 15;
    const int lcol = (lane >> 4) * 16;

    const int q0 = blockIdx.x * 128;
    const int bh = blockIdx.y;
    const int b = bh >> 4, h = bh & 15;

    const __half* Qg = Q + (size_t)bh * SEQ * DH + (size_t)q0 * DH;
    const __half* Kg = K + (size_t)bh * SEQ * DH;
    const __half* Vg = V + (size_t)bh * SEQ * DH;

    tile_load_64h(Qg, DH, smQ, tid);
    CP_COMMIT();
    tile_load_64h(Kg, DH, smem0 + 1 * FA_TILEB, tid);
    tile_load_64h(Vg, DH, smem0 + 3 * FA_TILEB, tid);
    CP_COMMIT();

    float m0 = -INFINITY, m1 = -INFINITY, l0 = 0.f, l1 = 0.f;
    float co[8][4];
#pragma unroll
    for (int nt = 0; nt < 8; nt++)
#pragma unroll
        for (int i = 0; i < 4; i++) co[nt][i] = 0.f;

    const uint32_t qBase = smQ + (uint32_t)((wid * 16 + lrow) * 144) + lcol;

    for (int t = 0; t < SEQ / 128; t++) {
        __syncthreads();   // everyone done reading buffer we overwrite next
        if (t + 1 < SEQ / 128) {
            const uint32_t koff = ((t + 1) & 1) ? 2u : 1u;
            tile_load_64h(Kg + (size_t)(t + 1) * 128 * DH, DH,
                          smem0 + koff * FA_TILEB, tid);
            tile_load_64h(Vg + (size_t)(t + 1) * 128 * DH, DH,
                          smem0 + (koff + 2) * FA_TILEB, tid);
            CP_COMMIT();
            CP_WAIT(1);
        } else {
            CP_WAIT(0);
        }
        __syncthreads();

        const uint32_t sK = smem0 + ((t & 1) ? 2u : 1u) * FA_TILEB;
        const uint32_t sV = smem0 + ((t & 1) ? 4u : 3u) * FA_TILEB;
        const uint32_t kBase = sK + (uint32_t)(lrow * 144) + lcol;
        const uint32_t vBase = sV + (uint32_t)(lrow * 144) + lcol;

        // ---- scores: S[16 x 128] = Q_tile @ K_tile^T ----
        float cs[16][4];
#pragma unroll
        for (int nt = 0; nt < 16; nt++)
#pragma unroll
            for (int i = 0; i < 4; i++) cs[nt][i] = 0.f;

#pragma unroll
        for (int ks = 0; ks < 4; ks++) {
            uint32_t a[4];
            ldm_x4(a, qBase + ks * 32);
#pragma unroll
            for (int np = 0; np < 8; np++) {
                uint32_t bb[4];
                ldm_x4(bb, kBase + (uint32_t)(np * 16 * 144) + ks * 32);
                mma_f16(cs[2*np],   a[0], a[1], a[2], a[3], bb[0], bb[2]);
                mma_f16(cs[2*np+1], a[0], a[1], a[2], a[3], bb[1], bb[3]);
            }
        }

        // ---- online softmax (rows g, g+8) ----
        float tm0 = -INFINITY, tm1 = -INFINITY;
#pragma unroll
        for (int nt = 0; nt < 16; nt++) {
            tm0 = fmaxf(tm0, fmaxf(cs[nt][0], cs[nt][1]));
            tm1 = fmaxf(tm1, fmaxf(cs[nt][2], cs[nt][3]));
        }
        tm0 = fmaxf(tm0, __shfl_xor_sync(0xffffffffu, tm0, 1));
        tm0 = fmaxf(tm0, __shfl_xor_sync(0xffffffffu, tm0, 2));
        tm1 = fmaxf(tm1, __shfl_xor_sync(0xffffffffu, tm1, 1));
        tm1 = fmaxf(tm1, __shfl_xor_sync(0xffffffffu, tm1, 2));

        const float mn0 = fmaxf(m0, tm0), mn1 = fmaxf(m1, tm1);
        const float corr0 = __expf(m0 - mn0), corr1 = __expf(m1 - mn1);
        m0 = mn0; m1 = mn1;

        float s0 = 0.f, s1 = 0.f;
#pragma unroll
        for (int nt = 0; nt < 16; nt++) {
            cs[nt][0] = __expf(cs[nt][0] - mn0);
            cs[nt][1] = __expf(cs[nt][1] - mn0);
            cs[nt][2] = __expf(cs[nt][2] - mn1);
            cs[nt][3] = __expf(cs[nt][3] - mn1);
            s0 += cs[nt][0] + cs[nt][1];
            s1 += cs[nt][2] + cs[nt][3];
        }
        s0 += __shfl_xor_sync(0xffffffffu, s0, 1);
        s0 += __shfl_xor_sync(0xffffffffu, s0, 2);
        s1 += __shfl_xor_sync(0xffffffffu, s1, 1);
        s1 += __shfl_xor_sync(0xffffffffu, s1, 2);
        l0 = l0 * corr0 + s0;
        l1 = l1 * corr1 + s1;

#pragma unroll
        for (int nt = 0; nt < 8; nt++) {
            co[nt][0] *= corr0; co[nt][1] *= corr0;
            co[nt][2] *= corr1; co[nt][3] *= corr1;
        }

        // ---- PV: out[16 x 64] += P[16 x 128] @ V[128 x 64] ----
#pragma unroll
        for (int j = 0; j < 8; j++) {
            const uint32_t a0 = pack2(cs[2*j][0],   cs[2*j][1]);
            const uint32_t a1 = pack2(cs[2*j][2],   cs[2*j][3]);
            const uint32_t a2 = pack2(cs[2*j+1][0], cs[2*j+1][1]);
            const uint32_t a3 = pack2(cs[2*j+1][2], cs[2*j+1][3]);
#pragma unroll
            for (int np = 0; np < 4; np++) {
                uint32_t bb[4];
                ldm_x4t(bb, vBase + (uint32_t)(j * 16 * 144) + np * 32);
                mma_f16(co[2*np],   a0, a1, a2, a3, bb[0], bb[1]);
                mma_f16(co[2*np+1], a0, a1, a2, a3, bb[2], bb[3]);
            }
        }
    }

    // ---- epilogue: normalize, write fp16 [B, S, H*dh] ----
    const float inv0 = 1.f / l0, inv1 = 1.f / l1;
    const int qrow = wid * 16 + g;
    __half* Og = Out + ((size_t)b * SEQ + (q0 + qrow)) * DM + h * DH;
#pragma unroll
    for (int nt = 0; nt < 8; nt++) {
        *(__half2*)(Og + 8 * nt + 2 * kq) =
            __floats2half2_rn(co[nt][0] * inv0, co[nt][1] * inv0);
        *(__half2*)(Og + (size_t)8 * DM + 8 * nt + 2 * kq) =
            __floats2half2_rn(co[nt][2] * inv1, co[nt][3] * inv1);
    }
}

// ---------------------------------------------------------------------------
// Launch
// ---------------------------------------------------------------------------
extern "C" void kernel_launch(void* const* d_in, const int* in_sizes, int n_in,
                              void* d_out, int out_size)
{
    const float* x  = (const float*)d_in[0];
    // d_in[1] = pH : constant along softmax axis -> provably no effect
    const float* Wq = (const float*)d_in[2];
    const float* bq = (const float*)d_in[3];
    const float* Wk = (const float*)d_in[4];
    const float* bk = (const float*)d_in[5];
    const float* Wv = (const float*)d_in[6];
    const float* bv = (const float*)d_in[7];
    const float* Wo = (const float*)d_in[8];
    const float* bo = (const float*)d_in[9];
    float* out = (float*)d_out;

    __half *x16, *qkv, *att, *wt, *wto;
    float *bias;
    cudaGetSymbolAddress((void**)&x16,  g_X16);
    cudaGetSymbolAddress((void**)&qkv,  g_QKV);
    cudaGetSymbolAddress((void**)&att,  g_ATT);
    cudaGetSymbolAddress((void**)&wt,   g_WT);
    cudaGetSymbolAddress((void**)&wto,  g_WTO);
    cudaGetSymbolAddress((void**)&bias, g_BIAS);

    cudaFuncSetAttribute(gemm_f16, cudaFuncAttributeMaxDynamicSharedMemorySize, TM_SMEM);
    cudaFuncSetAttribute(fa_mma, cudaFuncAttributeMaxDynamicSharedMemorySize, FA_SMEM);

    const float qscale = 0.125f;  // 1/sqrt(64), folded into Wq/bq

    // Prep
    f2h<<<MROWS * DM / 1024, 256>>>(x, x16);
    dim3 tb(32, 8), tg(32, 32);
    transpose_w<<<tg, tb>>>(Wq, wt, qscale);
    transpose_w<<<tg, tb>>>(Wk, wt + (size_t)DM * DM, 1.0f);
    transpose_w<<<tg, tb>>>(Wv, wt + 2 * (size_t)DM * DM, 1.0f);
    transpose_w<<<tg, tb>>>(Wo, wto, 1.0f);
    pack_bias<<<12, 256>>>(bq, bk, bv, bias);

    // Merged QKV projection: N = 3072
    dim3 gq(3 * DM / 128, MROWS / 128);   // (24, 32)
    gemm_f16<<<gq, 256, TM_SMEM>>>(x16, wt, bias, qkv, 0);

    // Attention
    dim3 ga(SEQ / 128, BATCH * NH);       // (16, 32)
    fa_mma<<<ga, 256, FA_SMEM>>>(qkv, qkv + QKV_OFF, qkv + 2 * QKV_OFF, att);

    // Output projection (fp32 out)
    dim3 go(DM / 128, MROWS / 128);       // (8, 32)
    gemm_f16<<<go, 256, TM_SMEM>>>(att, wto, bo, out, 1);
}

// round 6
// speedup vs baseline: 8.2854x; 1.0620x over previous
#include <cuda_runtime.h>
#include <cuda_fp16.h>
#include <math.h>
#include <stdint.h>

// Problem constants (fixed shapes)
#define BATCH 2
#define SEQ   2048
#define DM    1024
#define NH    16
#define DH    64
#define MROWS (BATCH*SEQ)          // 4096
#define QKV_OFF (BATCH*NH*SEQ*DH)  // 4194304

// Scratch (device globals; allocation-free)
__device__ __half g_X16[MROWS*DM];   // x converted to fp16
__device__ __half g_QKV[3*QKV_OFF];  // Q | K | V in [B,H,S,dh], fp16
__device__ __half g_ATT[MROWS*DM];   // attention output, fp16
__device__ __half g_WT[3*DM*DM];     // Wq^T | Wk^T | Wv^T (K-major [N,K]) fp16
__device__ __half g_WTO[DM*DM];      // Wo^T fp16
__device__ float  g_BIAS[3*DM];      // packed bq*s | bk | bv (fp32)

// ===========================================================================
// Helpers (baseline sm_80 PTX only — no 'a'-gated features)
// ===========================================================================
__device__ __forceinline__ void cp16(uint32_t s, const void* g) {
    asm volatile("cp.async.cg.shared.global [%0], [%1], 16;" :: "r"(s), "l"(g));
}
#define CP_COMMIT() asm volatile("cp.async.commit_group;" ::: "memory")
#define CP_WAIT(N)  asm volatile("cp.async.wait_group %0;" :: "n"(N) : "memory")

__device__ __forceinline__ void ldm_x4(uint32_t r[4], uint32_t a) {
    asm volatile("ldmatrix.sync.aligned.m8n8.x4.shared.b16 {%0,%1,%2,%3}, [%4];"
                 : "=r"(r[0]), "=r"(r[1]), "=r"(r[2]), "=r"(r[3]) : "r"(a));
}
__device__ __forceinline__ void ldm_x4t(uint32_t r[4], uint32_t a) {
    asm volatile("ldmatrix.sync.aligned.m8n8.x4.trans.shared.b16 {%0,%1,%2,%3}, [%4];"
                 : "=r"(r[0]), "=r"(r[1]), "=r"(r[2]), "=r"(r[3]) : "r"(a));
}

__device__ __forceinline__ void mma_f16(float c[4],
    uint32_t a0, uint32_t a1, uint32_t a2, uint32_t a3,
    uint32_t b0, uint32_t b1)
{
    asm volatile(
        "mma.sync.aligned.m16n8k16.row.col.f32.f16.f16.f32 "
        "{%0,%1,%2,%3}, {%4,%5,%6,%7}, {%8,%9}, {%0,%1,%2,%3};"
        : "+f"(c[0]), "+f"(c[1]), "+f"(c[2]), "+f"(c[3])
        : "r"(a0), "r"(a1), "r"(a2), "r"(a3), "r"(b0), "r"(b1));
}

__device__ __forceinline__ uint32_t pack2(float a, float b) {
    __half2 h = __floats2half2_rn(a, b);
    return *(uint32_t*)&h;
}

// ===========================================================================
// Fused prep kernel (one launch):
//   blocks [0,1024)        : f2h of x (fp32 -> fp16)
//   blocks [1024,5120)     : 4 weight transposes (fp32 [K,N] -> fp16 [N,K])
//   block  5120            : bias pack
// ===========================================================================
__global__ void __launch_bounds__(256) prep(
    const float* __restrict__ x,
    const float* __restrict__ Wq, const float* __restrict__ Wk,
    const float* __restrict__ Wv, const float* __restrict__ Wo,
    const float* __restrict__ bq, const float* __restrict__ bk,
    const float* __restrict__ bv,
    __half* __restrict__ x16, __half* __restrict__ wt,
    __half* __restrict__ wto, float* __restrict__ bias)
{
    const int blk = blockIdx.x;
    const int tid = threadIdx.x;

    if (blk < 1024) {
        // f2h: 1024 float4 per block
#pragma unroll
        for (int p = 0; p < 4; p++) {
            const int j = blk * 1024 + p * 256 + tid;   // float4 index
            float4 v = *(const float4*)(x + (size_t)j * 4);
            *(__half2*)(x16 + (size_t)j * 4)     = __floats2half2_rn(v.x, v.y);
            *(__half2*)(x16 + (size_t)j * 4 + 2) = __floats2half2_rn(v.z, v.w);
        }
        return;
    }
    if (blk < 5120) {
        // transpose: which in 0..3, 1024 blocks each of a 32x32 tile
        const int which = (blk - 1024) >> 10;
        const int bi = (blk - 1024) & 1023;
        const int bx = (bi & 31) * 32, by = (bi >> 5) * 32;
        const float* W = (which == 0) ? Wq : (which == 1) ? Wk : (which == 2) ? Wv : Wo;
        __half* D = (which == 3) ? wto : wt + (size_t)which * DM * DM;
        const float scale = (which == 0) ? 0.125f : 1.0f;

        __shared__ float t[32][33];
        const int xx = tid & 31, y4 = tid >> 5;   // y4: 0..7
#pragma unroll
        for (int i = 0; i < 4; i++) {
            const int row = by + y4 * 4 + i;
            t[y4 * 4 + i][xx] = W[(size_t)row * DM + bx + xx] * scale;
        }
        __syncthreads();
#pragma unroll
        for (int i = 0; i < 4; i++) {
            const int row = bx + y4 * 4 + i;
            D[(size_t)row * DM + by + xx] = __float2half(t[xx][y4 * 4 + i]);
        }
        return;
    }
    // bias pack
#pragma unroll
    for (int j = 0; j < 12; j++) {
        const int i = j * 256 + tid;
        float v;
        if (i < 1024)       v = bq[i] * 0.125f;
        else if (i < 2048)  v = bk[i - 1024];
        else                v = bv[i - 2048];
        bias[i] = v;
    }
}

// ===========================================================================
// FP16 mma GEMM v2: C[4096, N] = A[4096,1024] @ BT^T + bias
//   Block 256x128, 8 warps (4m x 2n), warp tile 64x64. BK=64, double buffer.
//   mode 0: QKV merged (N=3072): out -> 3 x [B,H,S,dh] fp16.
//   mode 1: out fp32 row-major [M,1024].
// SMEM rows: 64 halfs padded to 72 (144B) — ldmatrix conflict-free.
// ===========================================================================
#define ROWB 144
#define GA_TILEB (256 * ROWB)                 // 36864 A stage
#define GB_TILEB (128 * ROWB)                 // 18432 B stage
#define G_STAGE  (GA_TILEB + GB_TILEB)        // 55296
#define G_SMEM   (2 * G_STAGE)                // 110592

__device__ __forceinline__ void g_load_A(
    const __half* __restrict__ G, uint32_t sbase, int tid)
{
#pragma unroll
    for (int i = 0; i < 8; i++) {             // 256 rows x 8 seg
        const int idx = tid + (i << 8);
        const int r = idx >> 3, s = idx & 7;
        cp16(sbase + (uint32_t)(r * ROWB + s * 16), G + (size_t)r * DM + s * 8);
    }
}
__device__ __forceinline__ void g_load_B(
    const __half* __restrict__ G, uint32_t sbase, int tid)
{
#pragma unroll
    for (int i = 0; i < 4; i++) {             // 128 rows x 8 seg
        const int idx = tid + (i << 8);
        const int r = idx >> 3, s = idx & 7;
        cp16(sbase + (uint32_t)(r * ROWB + s * 16), G + (size_t)r * DM + s * 8);
    }
}

__global__ void __launch_bounds__(256) gemm_f16(
    const __half* __restrict__ A, const __half* __restrict__ BT,
    const float* __restrict__ bias, void* __restrict__ Cout, int mode)
{
    extern __shared__ __align__(16) char smraw[];
    const uint32_t smem0 = (uint32_t)__cvta_generic_to_shared(smraw);

    const int tid  = threadIdx.x;
    const int wid  = tid >> 5, lane = tid & 31;
    const int wm   = wid >> 1, wn = wid & 1;   // 4m x 2n
    const int g    = lane >> 2, kq = lane & 3;
    const int lrow = lane & 15;
    const int lcol = (lane >> 4) * 16;

    const int m0 = blockIdx.y * 256;
    const int n0 = blockIdx.x * 128;

    const __half* Ag = A  + (size_t)m0 * DM;
    const __half* Bg = BT + (size_t)n0 * DM;

    float c[4][8][4];
#pragma unroll
    for (int mt = 0; mt < 4; mt++)
#pragma unroll
        for (int nt = 0; nt < 8; nt++)
#pragma unroll
            for (int i = 0; i < 4; i++) c[mt][nt][i] = 0.f;

    g_load_A(Ag, smem0, tid);
    g_load_B(Bg, smem0 + GA_TILEB, tid);
    CP_COMMIT();

    const int NCH = DM / 64;                   // 16
    for (int kc = 0; kc < NCH; kc++) {
        if (kc + 1 < NCH) {
            const uint32_t sb = smem0 + (((kc + 1) & 1) ? (uint32_t)G_STAGE : 0u);
            g_load_A(Ag + (kc + 1) * 64, sb, tid);
            g_load_B(Bg + (kc + 1) * 64, sb + GA_TILEB, tid);
            CP_COMMIT();
            CP_WAIT(1);
        } else {
            CP_WAIT(0);
        }
        __syncthreads();

        const uint32_t sA = smem0 + ((kc & 1) ? (uint32_t)G_STAGE : 0u);
        const uint32_t sB = sA + GA_TILEB;
        const uint32_t aBase = sA + (uint32_t)((wm * 64 + lrow) * ROWB) + lcol;
        const uint32_t bBase = sB + (uint32_t)((wn * 64 + lrow) * ROWB) + lcol;

#pragma unroll
        for (int ks = 0; ks < 4; ks++) {       // 4 x k16
            uint32_t af[4][4], bf[4][4];
#pragma unroll
            for (int mt = 0; mt < 4; mt++)
                ldm_x4(af[mt], aBase + (uint32_t)(mt * 16 * ROWB) + ks * 32);
#pragma unroll
            for (int np = 0; np < 4; np++)
                ldm_x4(bf[np], bBase + (uint32_t)(np * 16 * ROWB) + ks * 32);
#pragma unroll
            for (int mt = 0; mt < 4; mt++) {
#pragma unroll
                for (int np = 0; np < 4; np++) {
                    mma_f16(c[mt][2*np],   af[mt][0], af[mt][1], af[mt][2], af[mt][3],
                            bf[np][0], bf[np][2]);
                    mma_f16(c[mt][2*np+1], af[mt][0], af[mt][1], af[mt][2], af[mt][3],
                            bf[np][1], bf[np][3]);
                }
            }
        }
        __syncthreads();
    }

    // Epilogue
#pragma unroll
    for (int mt = 0; mt < 4; mt++) {
        const int r1 = m0 + wm * 64 + mt * 16 + g;
        const int r2 = r1 + 8;
        const int b1 = r1 >> 11, s1 = r1 & 2047;
        const int b2 = r2 >> 11, s2 = r2 & 2047;
#pragma unroll
        for (int nt = 0; nt < 8; nt++) {
            const int n = n0 + wn * 64 + nt * 8 + 2 * kq;
            const float bx = bias[n], by = bias[n + 1];
            const float v10 = c[mt][nt][0] + bx, v11 = c[mt][nt][1] + by;
            const float v20 = c[mt][nt][2] + bx, v21 = c[mt][nt][3] + by;
            if (mode == 0) {
                __half* C = (__half*)Cout;
                const int which = n >> 10;
                const int nn = n & 1023;
                const int h = nn >> 6, d = nn & 63;
                const size_t base = (size_t)which * QKV_OFF;
                *(__half2*)(C + base + (((size_t)(b1 * NH + h)) * SEQ + s1) * DH + d) =
                    __floats2half2_rn(v10, v11);
                *(__half2*)(C + base + (((size_t)(b2 * NH + h)) * SEQ + s2) * DH + d) =
                    __floats2half2_rn(v20, v21);
            } else {
                float* C = (float*)Cout;
                *(float2*)(C + (size_t)r1 * DM + n) = make_float2(v10, v11);
                *(float2*)(C + (size_t)r2 * DM + n) = make_float2(v20, v21);
            }
        }
    }
}

// ===========================================================================
// Flash attention v2, FP16 mma. 4 warps/block (128 thr), m32 q-rows per warp,
// q-tile 128, BK=128. Q/K/V fp16 [B,H,S,dh]. Output fp16 [B,S,H*dh].
// ===========================================================================
#define FA_TILEB (128 * ROWB)                 // 18432 B
#define FA_SMEM (5 * FA_TILEB)                // Q + 2K + 2V = 92160 B

__device__ __forceinline__ void fa_load_tile(
    const __half* __restrict__ G, uint32_t sbase, int tid)
{
#pragma unroll
    for (int i = 0; i < 8; i++) {             // 128 rows x 8 seg, 128 threads
        const int idx = tid + (i << 7);
        const int r = idx >> 3, s = idx & 7;
        cp16(sbase + (uint32_t)(r * ROWB + s * 16), G + (size_t)r * DH + s * 8);
    }
}

__global__ void __launch_bounds__(128) fa_mma(
    const __half* __restrict__ Q, const __half* __restrict__ K,
    const __half* __restrict__ V, __half* __restrict__ Out)
{
    extern __shared__ __align__(16) char smraw[];
    const uint32_t smem0 = (uint32_t)__cvta_generic_to_shared(smraw);
    const uint32_t smQ = smem0;

    const int tid = threadIdx.x;
    const int wid = tid >> 5, lane = tid & 31;
    const int g = lane >> 2, kq = lane & 3;
    const int lrow = lane & 15;
    const int lcol = (lane >> 4) * 16;

    const int q0 = blockIdx.x * 128;
    const int bh = blockIdx.y;
    const int b = bh >> 4, h = bh & 15;

    const __half* Qg = Q + (size_t)bh * SEQ * DH + (size_t)q0 * DH;
    const __half* Kg = K + (size_t)bh * SEQ * DH;
    const __half* Vg = V + (size_t)bh * SEQ * DH;

    fa_load_tile(Qg, smQ, tid);
    CP_COMMIT();
    fa_load_tile(Kg, smem0 + 1 * FA_TILEB, tid);
    fa_load_tile(Vg, smem0 + 3 * FA_TILEB, tid);
    CP_COMMIT();

    // per-thread row stats for rows (g, g+8) of each m16 half
    float mx[2][2], li[2][2];
    float co[2][8][4];
#pragma unroll
    for (int mh = 0; mh < 2; mh++) {
        mx[mh][0] = mx[mh][1] = -INFINITY;
        li[mh][0] = li[mh][1] = 0.f;
#pragma unroll
        for (int nt = 0; nt < 8; nt++)
#pragma unroll
            for (int i = 0; i < 4; i++) co[mh][nt][i] = 0.f;
    }

    const uint32_t qBase = smQ + (uint32_t)((wid * 32 + lrow) * ROWB) + lcol;

    for (int t = 0; t < SEQ / 128; t++) {
        __syncthreads();
        if (t + 1 < SEQ / 128) {
            const uint32_t koff = ((t + 1) & 1) ? 2u : 1u;
            fa_load_tile(Kg + (size_t)(t + 1) * 128 * DH, smem0 + koff * FA_TILEB, tid);
            fa_load_tile(Vg + (size_t)(t + 1) * 128 * DH, smem0 + (koff + 2) * FA_TILEB, tid);
            CP_COMMIT();
            CP_WAIT(1);
        } else {
            CP_WAIT(0);
        }
        __syncthreads();

        const uint32_t sK = smem0 + ((t & 1) ? 2u : 1u) * FA_TILEB;
        const uint32_t sV = smem0 + ((t & 1) ? 4u : 3u) * FA_TILEB;
        const uint32_t kBase = sK + (uint32_t)(lrow * ROWB) + lcol;
        const uint32_t vBase = sV + (uint32_t)(lrow * ROWB) + lcol;

        // ---- scores: S[32 x 128] = Q_tile @ K_tile^T ----
        float cs[2][16][4];
#pragma unroll
        for (int mh = 0; mh < 2; mh++)
#pragma unroll
            for (int nt = 0; nt < 16; nt++)
#pragma unroll
                for (int i = 0; i < 4; i++) cs[mh][nt][i] = 0.f;

#pragma unroll
        for (int ks = 0; ks < 4; ks++) {
            uint32_t a[2][4];
            ldm_x4(a[0], qBase + ks * 32);
            ldm_x4(a[1], qBase + (uint32_t)(16 * ROWB) + ks * 32);
#pragma unroll
            for (int np = 0; np < 8; np++) {
                uint32_t bb[4];
                ldm_x4(bb, kBase + (uint32_t)(np * 16 * ROWB) + ks * 32);
#pragma unroll
                for (int mh = 0; mh < 2; mh++) {
                    mma_f16(cs[mh][2*np],   a[mh][0], a[mh][1], a[mh][2], a[mh][3],
                            bb[0], bb[2]);
                    mma_f16(cs[mh][2*np+1], a[mh][0], a[mh][1], a[mh][2], a[mh][3],
                            bb[1], bb[3]);
                }
            }
        }

        // ---- online softmax + pack P to half2 ----
        uint32_t p[2][16][2];
#pragma unroll
        for (int mh = 0; mh < 2; mh++) {
            float tm0 = -INFINITY, tm1 = -INFINITY;
#pragma unroll
            for (int nt = 0; nt < 16; nt++) {
                tm0 = fmaxf(tm0, fmaxf(cs[mh][nt][0], cs[mh][nt][1]));
                tm1 = fmaxf(tm1, fmaxf(cs[mh][nt][2], cs[mh][nt][3]));
            }
            tm0 = fmaxf(tm0, __shfl_xor_sync(0xffffffffu, tm0, 1));
            tm0 = fmaxf(tm0, __shfl_xor_sync(0xffffffffu, tm0, 2));
            tm1 = fmaxf(tm1, __shfl_xor_sync(0xffffffffu, tm1, 1));
            tm1 = fmaxf(tm1, __shfl_xor_sync(0xffffffffu, tm1, 2));

            const float mn0 = fmaxf(mx[mh][0], tm0), mn1 = fmaxf(mx[mh][1], tm1);
            const float corr0 = __expf(mx[mh][0] - mn0);
            const float corr1 = __expf(mx[mh][1] - mn1);
            mx[mh][0] = mn0; mx[mh][1] = mn1;

            float s0 = 0.f, s1 = 0.f;
#pragma unroll
            for (int nt = 0; nt < 16; nt++) {
                const float e0 = __expf(cs[mh][nt][0] - mn0);
                const float e1 = __expf(cs[mh][nt][1] - mn0);
                const float e2 = __expf(cs[mh][nt][2] - mn1);
                const float e3 = __expf(cs[mh][nt][3] - mn1);
                s0 += e0 + e1; s1 += e2 + e3;
                p[mh][nt][0] = pack2(e0, e1);
                p[mh][nt][1] = pack2(e2, e3);
            }
            s0 += __shfl_xor_sync(0xffffffffu, s0, 1);
            s0 += __shfl_xor_sync(0xffffffffu, s0, 2);
            s1 += __shfl_xor_sync(0xffffffffu, s1, 1);
            s1 += __shfl_xor_sync(0xffffffffu, s1, 2);
            li[mh][0] = li[mh][0] * corr0 + s0;
            li[mh][1] = li[mh][1] * corr1 + s1;

#pragma unroll
            for (int nt = 0; nt < 8; nt++) {
                co[mh][nt][0] *= corr0; co[mh][nt][1] *= corr0;
                co[mh][nt][2] *= corr1; co[mh][nt][3] *= corr1;
            }
        }

        // ---- PV: out[32 x 64] += P[32 x 128] @ V[128 x 64] ----
#pragma unroll
        for (int j = 0; j < 8; j++) {
            uint32_t bb[4][4];
#pragma unroll
            for (int np = 0; np < 4; np++)
                ldm_x4t(bb[np], vBase + (uint32_t)(j * 16 * ROWB) + np * 32);
#pragma unroll
            for (int mh = 0; mh < 2; mh++) {
                const uint32_t a0 = p[mh][2*j][0];
                const uint32_t a1 = p[mh][2*j][1];
                const uint32_t a2 = p[mh][2*j+1][0];
                const uint32_t a3 = p[mh][2*j+1][1];
#pragma unroll
                for (int np = 0; np < 4; np++) {
                    mma_f16(co[mh][2*np],   a0, a1, a2, a3, bb[np][0], bb[np][1]);
                    mma_f16(co[mh][2*np+1], a0, a1, a2, a3, bb[np][2], bb[np][3]);
                }
            }
        }
    }

    // ---- epilogue: normalize, write fp16 [B, S, H*dh] ----
#pragma unroll
    for (int mh = 0; mh < 2; mh++) {
        const float inv0 = 1.f / li[mh][0], inv1 = 1.f / li[mh][1];
        const int qrow = wid * 32 + mh * 16 + g;
        __half* Og = Out + ((size_t)b * SEQ + (q0 + qrow)) * DM + h * DH;
#pragma unroll
        for (int nt = 0; nt < 8; nt++) {
            *(__half2*)(Og + 8 * nt + 2 * kq) =
                __floats2half2_rn(co[mh][nt][0] * inv0, co[mh][nt][1] * inv0);
            *(__half2*)(Og + (size_t)8 * DM + 8 * nt + 2 * kq) =
                __floats2half2_rn(co[mh][nt][2] * inv1, co[mh][nt][3] * inv1);
        }
    }
}

// ---------------------------------------------------------------------------
// Launch
// ---------------------------------------------------------------------------
extern "C" void kernel_launch(void* const* d_in, const int* in_sizes, int n_in,
                              void* d_out, int out_size)
{
    const float* x  = (const float*)d_in[0];
    // d_in[1] = pH : constant along softmax axis -> provably no effect
    const float* Wq = (const float*)d_in[2];
    const float* bq = (const float*)d_in[3];
    const float* Wk = (const float*)d_in[4];
    const float* bk = (const float*)d_in[5];
    const float* Wv = (const float*)d_in[6];
    const float* bv = (const float*)d_in[7];
    const float* Wo = (const float*)d_in[8];
    const float* bo = (const float*)d_in[9];
    float* out = (float*)d_out;

    __half *x16, *qkv, *att, *wt, *wto;
    float *bias;
    cudaGetSymbolAddress((void**)&x16,  g_X16);
    cudaGetSymbolAddress((void**)&qkv,  g_QKV);
    cudaGetSymbolAddress((void**)&att,  g_ATT);
    cudaGetSymbolAddress((void**)&wt,   g_WT);
    cudaGetSymbolAddress((void**)&wto,  g_WTO);
    cudaGetSymbolAddress((void**)&bias, g_BIAS);

    cudaFuncSetAttribute(gemm_f16, cudaFuncAttributeMaxDynamicSharedMemorySize, G_SMEM);
    cudaFuncSetAttribute(fa_mma, cudaFuncAttributeMaxDynamicSharedMemorySize, FA_SMEM);

    // Fused prep: f2h + 4 transposes + bias pack
    prep<<<5121, 256>>>(x, Wq, Wk, Wv, Wo, bq, bk, bv, x16, wt, wto, bias);

    // Merged QKV projection: N = 3072
    dim3 gq(3 * DM / 128, MROWS / 256);   // (24, 16)
    gemm_f16<<<gq, 256, G_SMEM>>>(x16, wt, bias, qkv, 0);

    // Attention
    dim3 ga(SEQ / 128, BATCH * NH);       // (16, 32)
    fa_mma<<<ga, 128, FA_SMEM>>>(qkv, qkv + QKV_OFF, qkv + 2 * QKV_OFF, att);

    // Output projection (fp32 out)
    dim3 go(DM / 128, MROWS / 256);       // (8, 16)
    gemm_f16<<<go, 256, G_SMEM>>>(att, wto, bo, out, 1);
}

// round 7
// speedup vs baseline: 8.7198x; 1.0524x over previous
#include <cuda_runtime.h>
#include <cuda_fp16.h>
#include <math.h>
#include <stdint.h>

// Problem constants (fixed shapes)
#define BATCH 2
#define SEQ   2048
#define DM    1024
#define NH    16
#define DH    64
#define MROWS (BATCH*SEQ)          // 4096
#define QKV_OFF (BATCH*NH*SEQ*DH)  // 4194304

// Scratch (device globals; allocation-free)
__device__ __half g_X16[MROWS*DM];
__device__ __half g_QKV[3*QKV_OFF];
__device__ __half g_ATT[MROWS*DM];
__device__ __half g_WT[3*DM*DM];
__device__ __half g_WTO[DM*DM];
__device__ float  g_BIAS[3*DM];

#define LOG2E 1.4426950408889634f

// ===========================================================================
// Helpers (baseline sm_80 PTX only)
// ===========================================================================
__device__ __forceinline__ void cp16(uint32_t s, const void* g) {
    asm volatile("cp.async.cg.shared.global [%0], [%1], 16;" :: "r"(s), "l"(g));
}
#define CP_COMMIT() asm volatile("cp.async.commit_group;" ::: "memory")
#define CP_WAIT(N)  asm volatile("cp.async.wait_group %0;" :: "n"(N) : "memory")

__device__ __forceinline__ void ldm_x4(uint32_t r[4], uint32_t a) {
    asm volatile("ldmatrix.sync.aligned.m8n8.x4.shared.b16 {%0,%1,%2,%3}, [%4];"
                 : "=r"(r[0]), "=r"(r[1]), "=r"(r[2]), "=r"(r[3]) : "r"(a));
}
__device__ __forceinline__ void ldm_x4t(uint32_t r[4], uint32_t a) {
    asm volatile("ldmatrix.sync.aligned.m8n8.x4.trans.shared.b16 {%0,%1,%2,%3}, [%4];"
                 : "=r"(r[0]), "=r"(r[1]), "=r"(r[2]), "=r"(r[3]) : "r"(a));
}

__device__ __forceinline__ void mma_f16(float c[4],
    uint32_t a0, uint32_t a1, uint32_t a2, uint32_t a3,
    uint32_t b0, uint32_t b1)
{
    asm volatile(
        "mma.sync.aligned.m16n8k16.row.col.f32.f16.f16.f32 "
        "{%0,%1,%2,%3}, {%4,%5,%6,%7}, {%8,%9}, {%0,%1,%2,%3};"
        : "+f"(c[0]), "+f"(c[1]), "+f"(c[2]), "+f"(c[3])
        : "r"(a0), "r"(a1), "r"(a2), "r"(a3), "r"(b0), "r"(b1));
}

__device__ __forceinline__ uint32_t pack2(float a, float b) {
    __half2 h = __floats2half2_rn(a, b);
    return *(uint32_t*)&h;
}
// 2^x on packed half2 — one MUFU op for two probabilities
__device__ __forceinline__ uint32_t ex2_h2(uint32_t x) {
    uint32_t r;
    asm("ex2.approx.f16x2 %0, %1;" : "=r"(r) : "r"(x));
    return r;
}

// ===========================================================================
// Fused prep kernel
// ===========================================================================
__global__ void __launch_bounds__(256) prep(
    const float* __restrict__ x,
    const float* __restrict__ Wq, const float* __restrict__ Wk,
    const float* __restrict__ Wv, const float* __restrict__ Wo,
    const float* __restrict__ bq, const float* __restrict__ bk,
    const float* __restrict__ bv,
    __half* __restrict__ x16, __half* __restrict__ wt,
    __half* __restrict__ wto, float* __restrict__ bias)
{
    const int blk = blockIdx.x;
    const int tid = threadIdx.x;
    const float qs = 0.125f * LOG2E;   // 1/sqrt(dh) * log2(e), folded into Wq/bq

    if (blk < 1024) {
#pragma unroll
        for (int p = 0; p < 4; p++) {
            const int j = blk * 1024 + p * 256 + tid;
            float4 v = *(const float4*)(x + (size_t)j * 4);
            *(__half2*)(x16 + (size_t)j * 4)     = __floats2half2_rn(v.x, v.y);
            *(__half2*)(x16 + (size_t)j * 4 + 2) = __floats2half2_rn(v.z, v.w);
        }
        return;
    }
    if (blk < 5120) {
        const int which = (blk - 1024) >> 10;
        const int bi = (blk - 1024) & 1023;
        const int bx = (bi & 31) * 32, by = (bi >> 5) * 32;
        const float* W = (which == 0) ? Wq : (which == 1) ? Wk : (which == 2) ? Wv : Wo;
        __half* D = (which == 3) ? wto : wt + (size_t)which * DM * DM;
        const float scale = (which == 0) ? qs : 1.0f;

        __shared__ float t[32][33];
        const int xx = tid & 31, y4 = tid >> 5;
#pragma unroll
        for (int i = 0; i < 4; i++) {
            const int row = by + y4 * 4 + i;
            t[y4 * 4 + i][xx] = W[(size_t)row * DM + bx + xx] * scale;
        }
        __syncthreads();
#pragma unroll
        for (int i = 0; i < 4; i++) {
            const int row = bx + y4 * 4 + i;
            D[(size_t)row * DM + by + xx] = __float2half(t[xx][y4 * 4 + i]);
        }
        return;
    }
#pragma unroll
    for (int j = 0; j < 12; j++) {
        const int i = j * 256 + tid;
        float v;
        if (i < 1024)       v = bq[i] * qs;
        else if (i < 2048)  v = bk[i - 1024];
        else                v = bv[i - 2048];
        bias[i] = v;
    }
}

// ===========================================================================
// FP16 mma GEMM v3: 512 threads, block 256x128, 16 warps (8m x 2n),
// warp tile 32x64, BK=64, 3-stage cp.async pipeline.
// ===========================================================================
#define ROWB 144
#define GA_TILEB (256 * ROWB)
#define GB_TILEB (128 * ROWB)
#define G_STAGE  (GA_TILEB + GB_TILEB)        // 55296
#define G_SMEM   (3 * G_STAGE)                // 165888

__device__ __forceinline__ void g_load_A(
    const __half* __restrict__ G, uint32_t sbase, int tid)
{
#pragma unroll
    for (int i = 0; i < 4; i++) {             // 256 rows x 8 seg / 512 thr
        const int idx = tid + (i << 9);
        const int r = idx >> 3, s = idx & 7;
        cp16(sbase + (uint32_t)(r * ROWB + s * 16), G + (size_t)r * DM + s * 8);
    }
}
__device__ __forceinline__ void g_load_B(
    const __half* __restrict__ G, uint32_t sbase, int tid)
{
#pragma unroll
    for (int i = 0; i < 2; i++) {             // 128 rows x 8 seg / 512 thr
        const int idx = tid + (i << 9);
        const int r = idx >> 3, s = idx & 7;
        cp16(sbase + (uint32_t)(r * ROWB + s * 16), G + (size_t)r * DM + s * 8);
    }
}

__global__ void __launch_bounds__(512, 1) gemm_f16(
    const __half* __restrict__ A, const __half* __restrict__ BT,
    const float* __restrict__ bias, void* __restrict__ Cout, int mode)
{
    extern __shared__ __align__(16) char smraw[];
    const uint32_t smem0 = (uint32_t)__cvta_generic_to_shared(smraw);

    const int tid  = threadIdx.x;
    const int wid  = tid >> 5, lane = tid & 31;
    const int wm   = wid >> 1, wn = wid & 1;   // 8m x 2n
    const int g    = lane >> 2, kq = lane & 3;
    const int lrow = lane & 15;
    const int lcol = (lane >> 4) * 16;

    const int m0 = blockIdx.y * 256;
    const int n0 = blockIdx.x * 128;

    const __half* Ag = A  + (size_t)m0 * DM;
    const __half* Bg = BT + (size_t)n0 * DM;

    float c[2][8][4];
#pragma unroll
    for (int mt = 0; mt < 2; mt++)
#pragma unroll
        for (int nt = 0; nt < 8; nt++)
#pragma unroll
            for (int i = 0; i < 4; i++) c[mt][nt][i] = 0.f;

    // Prologue: prefetch chunks 0 and 1
    g_load_A(Ag, smem0, tid);
    g_load_B(Bg, smem0 + GA_TILEB, tid);
    CP_COMMIT();
    g_load_A(Ag + 64, smem0 + G_STAGE, tid);
    g_load_B(Bg + 64, smem0 + G_STAGE + GA_TILEB, tid);
    CP_COMMIT();

    const int NCH = DM / 64;                   // 16
    for (int kc = 0; kc < NCH; kc++) {
        if (kc < NCH - 1) { CP_WAIT(1); } else { CP_WAIT(0); }
        __syncthreads();                       // all warps done with stage (kc+2)%3

        if (kc + 2 < NCH) {
            const uint32_t sb = smem0 + (uint32_t)(((kc + 2) % 3) * G_STAGE);
            g_load_A(Ag + (kc + 2) * 64, sb, tid);
            g_load_B(Bg + (kc + 2) * 64, sb + GA_TILEB, tid);
            CP_COMMIT();
        }

        const uint32_t sA = smem0 + (uint32_t)((kc % 3) * G_STAGE);
        const uint32_t sB = sA + GA_TILEB;
        const uint32_t aBase = sA + (uint32_t)((wm * 32 + lrow) * ROWB) + lcol;
        const uint32_t bBase = sB + (uint32_t)((wn * 64 + lrow) * ROWB) + lcol;

#pragma unroll
        for (int ks = 0; ks < 4; ks++) {       // 4 x k16
            uint32_t af[2][4], bf[4][4];
#pragma unroll
            for (int mt = 0; mt < 2; mt++)
                ldm_x4(af[mt], aBase + (uint32_t)(mt * 16 * ROWB) + ks * 32);
#pragma unroll
            for (int np = 0; np < 4; np++)
                ldm_x4(bf[np], bBase + (uint32_t)(np * 16 * ROWB) + ks * 32);
#pragma unroll
            for (int mt = 0; mt < 2; mt++) {
#pragma unroll
                for (int np = 0; np < 4; np++) {
                    mma_f16(c[mt][2*np],   af[mt][0], af[mt][1], af[mt][2], af[mt][3],
                            bf[np][0], bf[np][2]);
                    mma_f16(c[mt][2*np+1], af[mt][0], af[mt][1], af[mt][2], af[mt][3],
                            bf[np][1], bf[np][3]);
                }
            }
        }
    }

    // Epilogue
#pragma unroll
    for (int mt = 0; mt < 2; mt++) {
        const int r1 = m0 + wm * 32 + mt * 16 + g;
        const int r2 = r1 + 8;
        const int b1 = r1 >> 11, s1 = r1 & 2047;
        const int b2 = r2 >> 11, s2 = r2 & 2047;
#pragma unroll
        for (int nt = 0; nt < 8; nt++) {
            const int n = n0 + wn * 64 + nt * 8 + 2 * kq;
            const float bx = bias[n], by = bias[n + 1];
            const float v10 = c[mt][nt][0] + bx, v11 = c[mt][nt][1] + by;
            const float v20 = c[mt][nt][2] + bx, v21 = c[mt][nt][3] + by;
            if (mode == 0) {
                __half* C = (__half*)Cout;
                const int which = n >> 10;
                const int nn = n & 1023;
                const int h = nn >> 6, d = nn & 63;
                const size_t base = (size_t)which * QKV_OFF;
                *(__half2*)(C + base + (((size_t)(b1 * NH + h)) * SEQ + s1) * DH + d) =
                    __floats2half2_rn(v10, v11);
                *(__half2*)(C + base + (((size_t)(b2 * NH + h)) * SEQ + s2) * DH + d) =
                    __floats2half2_rn(v20, v21);
            } else {
                float* C = (float*)Cout;
                *(float2*)(C + (size_t)r1 * DM + n) = make_float2(v10, v11);
                *(float2*)(C + (size_t)r2 * DM + n) = make_float2(v20, v21);
            }
        }
    }
}

// ===========================================================================
// Flash attention v3, FP16 mma. 4 warps/block, m32/warp, q-tile 128, BK=128.
// Scores arrive in log2 domain (log2e folded into Wq/bq). P = ex2.f16x2.
// Row sums via ones-column MMA. Output fp16 [B,S,H*dh].
// ===========================================================================
#define FA_TILEB (128 * ROWB)
#define FA_SMEM (5 * FA_TILEB)                // 92160 B -> 2 CTAs/SM

#define ONES_H2 0x3C003C00u

__device__ __forceinline__ void fa_load_tile(
    const __half* __restrict__ G, uint32_t sbase, int tid)
{
#pragma unroll
    for (int i = 0; i < 8; i++) {
        const int idx = tid + (i << 7);
        const int r = idx >> 3, s = idx & 7;
        cp16(sbase + (uint32_t)(r * ROWB + s * 16), G + (size_t)r * DH + s * 8);
    }
}

__global__ void __launch_bounds__(128) fa_mma(
    const __half* __restrict__ Q, const __half* __restrict__ K,
    const __half* __restrict__ V, __half* __restrict__ Out)
{
    extern __shared__ __align__(16) char smraw[];
    const uint32_t smem0 = (uint32_t)__cvta_generic_to_shared(smraw);
    const uint32_t smQ = smem0;

    const int tid = threadIdx.x;
    const int wid = tid >> 5, lane = tid & 31;
    const int g = lane >> 2, kq = lane & 3;
    const int lrow = lane & 15;
    const int lcol = (lane >> 4) * 16;

    const int q0 = blockIdx.x * 128;
    const int bh = blockIdx.y;
    const int b = bh >> 4, h = bh & 15;

    const __half* Qg = Q + (size_t)bh * SEQ * DH + (size_t)q0 * DH;
    const __half* Kg = K + (size_t)bh * SEQ * DH;
    const __half* Vg = V + (size_t)bh * SEQ * DH;

    fa_load_tile(Qg, smQ, tid);
    CP_COMMIT();
    fa_load_tile(Kg, smem0 + 1 * FA_TILEB, tid);
    fa_load_tile(Vg, smem0 + 3 * FA_TILEB, tid);
    CP_COMMIT();

    float mx[2][2], li[2][2];
    float co[2][8][4];
#pragma unroll
    for (int mh = 0; mh < 2; mh++) {
        mx[mh][0] = mx[mh][1] = -INFINITY;
        li[mh][0] = li[mh][1] = 0.f;
#pragma unroll
        for (int nt = 0; nt < 8; nt++)
#pragma unroll
            for (int i = 0; i < 4; i++) co[mh][nt][i] = 0.f;
    }

    const uint32_t qBase = smQ + (uint32_t)((wid * 32 + lrow) * ROWB) + lcol;

    for (int t = 0; t < SEQ / 128; t++) {
        __syncthreads();
        if (t + 1 < SEQ / 128) {
            const uint32_t koff = ((t + 1) & 1) ? 2u : 1u;
            fa_load_tile(Kg + (size_t)(t + 1) * 128 * DH, smem0 + koff * FA_TILEB, tid);
            fa_load_tile(Vg + (size_t)(t + 1) * 128 * DH, smem0 + (koff + 2) * FA_TILEB, tid);
            CP_COMMIT();
            CP_WAIT(1);
        } else {
            CP_WAIT(0);
        }
        __syncthreads();

        const uint32_t sK = smem0 + ((t & 1) ? 2u : 1u) * FA_TILEB;
        const uint32_t sV = smem0 + ((t & 1) ? 4u : 3u) * FA_TILEB;
        const uint32_t kBase = sK + (uint32_t)(lrow * ROWB) + lcol;
        const uint32_t vBase = sV + (uint32_t)(lrow * ROWB) + lcol;

        // ---- scores (log2 domain): S[32 x 128] = Q @ K^T ----
        float cs[2][16][4];
#pragma unroll
        for (int mh = 0; mh < 2; mh++)
#pragma unroll
            for (int nt = 0; nt < 16; nt++)
#pragma unroll
                for (int i = 0; i < 4; i++) cs[mh][nt][i] = 0.f;

#pragma unroll
        for (int ks = 0; ks < 4; ks++) {
            uint32_t a[2][4];
            ldm_x4(a[0], qBase + ks * 32);
            ldm_x4(a[1], qBase + (uint32_t)(16 * ROWB) + ks * 32);
#pragma unroll
            for (int np = 0; np < 8; np++) {
                uint32_t bb[4];
                ldm_x4(bb, kBase + (uint32_t)(np * 16 * ROWB) + ks * 32);
#pragma unroll
                for (int mh = 0; mh < 2; mh++) {
                    mma_f16(cs[mh][2*np],   a[mh][0], a[mh][1], a[mh][2], a[mh][3],
                            bb[0], bb[2]);
                    mma_f16(cs[mh][2*np+1], a[mh][0], a[mh][1], a[mh][2], a[mh][3],
                            bb[1], bb[3]);
                }
            }
        }

        // ---- online softmax: max (fp32, FMA pipe) + P = 2^(s-m) via f16x2 MUFU ----
        uint32_t p[2][16][2];
        float corr[2][2];
#pragma unroll
        for (int mh = 0; mh < 2; mh++) {
            float tm0 = -INFINITY, tm1 = -INFINITY;
#pragma unroll
            for (int nt = 0; nt < 16; nt++) {
                tm0 = fmaxf(tm0, fmaxf(cs[mh][nt][0], cs[mh][nt][1]));
                tm1 = fmaxf(tm1, fmaxf(cs[mh][nt][2], cs[mh][nt][3]));
            }
            tm0 = fmaxf(tm0, __shfl_xor_sync(0xffffffffu, tm0, 1));
            tm0 = fmaxf(tm0, __shfl_xor_sync(0xffffffffu, tm0, 2));
            tm1 = fmaxf(tm1, __shfl_xor_sync(0xffffffffu, tm1, 1));
            tm1 = fmaxf(tm1, __shfl_xor_sync(0xffffffffu, tm1, 2));

            const float mn0 = fmaxf(mx[mh][0], tm0), mn1 = fmaxf(mx[mh][1], tm1);
            corr[mh][0] = exp2f(mx[mh][0] - mn0);
            corr[mh][1] = exp2f(mx[mh][1] - mn1);
            mx[mh][0] = mn0; mx[mh][1] = mn1;

#pragma unroll
            for (int nt = 0; nt < 16; nt++) {
                p[mh][nt][0] = ex2_h2(pack2(cs[mh][nt][0] - mn0, cs[mh][nt][1] - mn0));
                p[mh][nt][1] = ex2_h2(pack2(cs[mh][nt][2] - mn1, cs[mh][nt][3] - mn1));
            }

#pragma unroll
            for (int nt = 0; nt < 8; nt++) {
                co[mh][nt][0] *= corr[mh][0]; co[mh][nt][1] *= corr[mh][0];
                co[mh][nt][2] *= corr[mh][1]; co[mh][nt][3] *= corr[mh][1];
            }
        }

        // ---- PV + row-sum via ones-MMA ----
        float lacc[2][4];
#pragma unroll
        for (int mh = 0; mh < 2; mh++)
#pragma unroll
            for (int i = 0; i < 4; i++) lacc[mh][i] = 0.f;

#pragma unroll
        for (int j = 0; j < 8; j++) {
            uint32_t bb[4][4];
#pragma unroll
            for (int np = 0; np < 4; np++)
                ldm_x4t(bb[np], vBase + (uint32_t)(j * 16 * ROWB) + np * 32);
#pragma unroll
            for (int mh = 0; mh < 2; mh++) {
                const uint32_t a0 = p[mh][2*j][0];
                const uint32_t a1 = p[mh][2*j][1];
                const uint32_t a2 = p[mh][2*j+1][0];
                const uint32_t a3 = p[mh][2*j+1][1];
#pragma unroll
                for (int np = 0; np < 4; np++) {
                    mma_f16(co[mh][2*np],   a0, a1, a2, a3, bb[np][0], bb[np][1]);
                    mma_f16(co[mh][2*np+1], a0, a1, a2, a3, bb[np][2], bb[np][3]);
                }
                mma_f16(lacc[mh], a0, a1, a2, a3, ONES_H2, ONES_H2);
            }
        }

#pragma unroll
        for (int mh = 0; mh < 2; mh++) {
            li[mh][0] = li[mh][0] * corr[mh][0] + lacc[mh][0];
            li[mh][1] = li[mh][1] * corr[mh][1] + lacc[mh][2];
        }
    }

    // ---- epilogue: normalize, write fp16 [B, S, H*dh] ----
#pragma unroll
    for (int mh = 0; mh < 2; mh++) {
        const float inv0 = 1.f / li[mh][0], inv1 = 1.f / li[mh][1];
        const int qrow = wid * 32 + mh * 16 + g;
        __half* Og = Out + ((size_t)b * SEQ + (q0 + qrow)) * DM + h * DH;
#pragma unroll
        for (int nt = 0; nt < 8; nt++) {
            *(__half2*)(Og + 8 * nt + 2 * kq) =
                __floats2half2_rn(co[mh][nt][0] * inv0, co[mh][nt][1] * inv0);
            *(__half2*)(Og + (size_t)8 * DM + 8 * nt + 2 * kq) =
                __floats2half2_rn(co[mh][nt][2] * inv1, co[mh][nt][3] * inv1);
        }
    }
}

// ---------------------------------------------------------------------------
// Launch
// ---------------------------------------------------------------------------
extern "C" void kernel_launch(void* const* d_in, const int* in_sizes, int n_in,
                              void* d_out, int out_size)
{
    const float* x  = (const float*)d_in[0];
    // d_in[1] = pH : constant along softmax axis -> provably no effect
    const float* Wq = (const float*)d_in[2];
    const float* bq = (const float*)d_in[3];
    const float* Wk = (const float*)d_in[4];
    const float* bk = (const float*)d_in[5];
    const float* Wv = (const float*)d_in[6];
    const float* bv = (const float*)d_in[7];
    const float* Wo = (const float*)d_in[8];
    const float* bo = (const float*)d_in[9];
    float* out = (float*)d_out;

    __half *x16, *qkv, *att, *wt, *wto;
    float *bias;
    cudaGetSymbolAddress((void**)&x16,  g_X16);
    cudaGetSymbolAddress((void**)&qkv,  g_QKV);
    cudaGetSymbolAddress((void**)&att,  g_ATT);
    cudaGetSymbolAddress((void**)&wt,   g_WT);
    cudaGetSymbolAddress((void**)&wto,  g_WTO);
    cudaGetSymbolAddress((void**)&bias, g_BIAS);

    cudaFuncSetAttribute(gemm_f16, cudaFuncAttributeMaxDynamicSharedMemorySize, G_SMEM);
    cudaFuncSetAttribute(fa_mma, cudaFuncAttributeMaxDynamicSharedMemorySize, FA_SMEM);

    // Fused prep: f2h + 4 transposes + bias pack (log2e folded into Wq/bq)
    prep<<<5121, 256>>>(x, Wq, Wk, Wv, Wo, bq, bk, bv, x16, wt, wto, bias);

    // Merged QKV projection: N = 3072
    dim3 gq(3 * DM / 128, MROWS / 256);   // (24, 16)
    gemm_f16<<<gq, 512, G_SMEM>>>(x16, wt, bias, qkv, 0);

    // Attention
    dim3 ga(SEQ / 128, BATCH * NH);       // (16, 32)
    fa_mma<<<ga, 128, FA_SMEM>>>(qkv, qkv + QKV_OFF, qkv + 2 * QKV_OFF, att);

    // Output projection (fp32 out)
    dim3 go(DM / 128, MROWS / 256);       // (8, 16)
    gemm_f16<<<go, 512, G_SMEM>>>(att, wto, bo, out, 1);
}

// round 8
// speedup vs baseline: 8.8580x; 1.0159x over previous
#include <cuda_runtime.h>
#include <cuda_fp16.h>
#include <math.h>
#include <stdint.h>

// Problem constants (fixed shapes)
#define BATCH 2
#define SEQ   2048
#define DM    1024
#define NH    16
#define DH    64
#define MROWS (BATCH*SEQ)          // 4096
#define QKV_OFF (BATCH*NH*SEQ*DH)  // 4194304

// Scratch (device globals; allocation-free)
__device__ __half g_X16[MROWS*DM];
__device__ __half g_QKV[3*QKV_OFF];
__device__ __half g_ATT[MROWS*DM];
__device__ __half g_WT[3*DM*DM];
__device__ __half g_WTO[DM*DM];
__device__ float  g_BIAS[3*DM];

#define LOG2E 1.4426950408889634f

// ===========================================================================
// Helpers (baseline sm_80 PTX only)
// ===========================================================================
__device__ __forceinline__ void cp16(uint32_t s, const void* g) {
    asm volatile("cp.async.cg.shared.global [%0], [%1], 16;" :: "r"(s), "l"(g));
}
#define CP_COMMIT() asm volatile("cp.async.commit_group;" ::: "memory")
#define CP_WAIT(N)  asm volatile("cp.async.wait_group %0;" :: "n"(N) : "memory")

__device__ __forceinline__ void ldm_x4(uint32_t r[4], uint32_t a) {
    asm volatile("ldmatrix.sync.aligned.m8n8.x4.shared.b16 {%0,%1,%2,%3}, [%4];"
                 : "=r"(r[0]), "=r"(r[1]), "=r"(r[2]), "=r"(r[3]) : "r"(a));
}
__device__ __forceinline__ void ldm_x4t(uint32_t r[4], uint32_t a) {
    asm volatile("ldmatrix.sync.aligned.m8n8.x4.trans.shared.b16 {%0,%1,%2,%3}, [%4];"
                 : "=r"(r[0]), "=r"(r[1]), "=r"(r[2]), "=r"(r[3]) : "r"(a));
}

// f32-accumulate MMA (rt16)
__device__ __forceinline__ void mma_f16(float c[4],
    uint32_t a0, uint32_t a1, uint32_t a2, uint32_t a3,
    uint32_t b0, uint32_t b1)
{
    asm volatile(
        "mma.sync.aligned.m16n8k16.row.col.f32.f16.f16.f32 "
        "{%0,%1,%2,%3}, {%4,%5,%6,%7}, {%8,%9}, {%0,%1,%2,%3};"
        : "+f"(c[0]), "+f"(c[1]), "+f"(c[2]), "+f"(c[3])
        : "r"(a0), "r"(a1), "r"(a2), "r"(a3), "r"(b0), "r"(b1));
}

// f16-accumulate MMA (rt8 — 2x rate). c[0]={row g, cols 2kq,2kq+1}, c[1]={row g+8,...}
__device__ __forceinline__ void mma_f16acc(uint32_t c[2],
    uint32_t a0, uint32_t a1, uint32_t a2, uint32_t a3,
    uint32_t b0, uint32_t b1)
{
    asm volatile(
        "mma.sync.aligned.m16n8k16.row.col.f16.f16.f16.f16 "
        "{%0,%1}, {%2,%3,%4,%5}, {%6,%7}, {%0,%1};"
        : "+r"(c[0]), "+r"(c[1])
        : "r"(a0), "r"(a1), "r"(a2), "r"(a3), "r"(b0), "r"(b1));
}

__device__ __forceinline__ uint32_t ex2_h2(uint32_t x) {
    uint32_t r;
    asm("ex2.approx.f16x2 %0, %1;" : "=r"(r) : "r"(x));
    return r;
}
__device__ __forceinline__ uint32_t hsub2_u(uint32_t a, uint32_t b) {
    __half2 r = __hsub2(*(__half2*)&a, *(__half2*)&b);
    return *(uint32_t*)&r;
}

// ===========================================================================
// Fused prep kernel
// ===========================================================================
__global__ void __launch_bounds__(256) prep(
    const float* __restrict__ x,
    const float* __restrict__ Wq, const float* __restrict__ Wk,
    const float* __restrict__ Wv, const float* __restrict__ Wo,
    const float* __restrict__ bq, const float* __restrict__ bk,
    const float* __restrict__ bv,
    __half* __restrict__ x16, __half* __restrict__ wt,
    __half* __restrict__ wto, float* __restrict__ bias)
{
    const int blk = blockIdx.x;
    const int tid = threadIdx.x;
    const float qs = 0.125f * LOG2E;

    if (blk < 1024) {
#pragma unroll
        for (int p = 0; p < 4; p++) {
            const int j = blk * 1024 + p * 256 + tid;
            float4 v = *(const float4*)(x + (size_t)j * 4);
            *(__half2*)(x16 + (size_t)j * 4)     = __floats2half2_rn(v.x, v.y);
            *(__half2*)(x16 + (size_t)j * 4 + 2) = __floats2half2_rn(v.z, v.w);
        }
        return;
    }
    if (blk < 5120) {
        const int which = (blk - 1024) >> 10;
        const int bi = (blk - 1024) & 1023;
        const int bx = (bi & 31) * 32, by = (bi >> 5) * 32;
        const float* W = (which == 0) ? Wq : (which == 1) ? Wk : (which == 2) ? Wv : Wo;
        __half* D = (which == 3) ? wto : wt + (size_t)which * DM * DM;
        const float scale = (which == 0) ? qs : 1.0f;

        __shared__ float t[32][33];
        const int xx = tid & 31, y4 = tid >> 5;
#pragma unroll
        for (int i = 0; i < 4; i++) {
            const int row = by + y4 * 4 + i;
            t[y4 * 4 + i][xx] = W[(size_t)row * DM + bx + xx] * scale;
        }
        __syncthreads();
#pragma unroll
        for (int i = 0; i < 4; i++) {
            const int row = bx + y4 * 4 + i;
            D[(size_t)row * DM + by + xx] = __float2half(t[xx][y4 * 4 + i]);
        }
        return;
    }
#pragma unroll
    for (int j = 0; j < 12; j++) {
        const int i = j * 256 + tid;
        float v;
        if (i < 1024)       v = bq[i] * qs;
        else if (i < 2048)  v = bk[i - 1024];
        else                v = bv[i - 2048];
        bias[i] = v;
    }
}

// ===========================================================================
// FP16 mma GEMM (f32 acc, at tensor ceiling): 512 thr, block 256x128,
// 16 warps (8m x 2n), warp tile 32x64, BK=64, 3-stage cp.async.
// ===========================================================================
#define ROWB 144
#define GA_TILEB (256 * ROWB)
#define GB_TILEB (128 * ROWB)
#define G_STAGE  (GA_TILEB + GB_TILEB)
#define G_SMEM   (3 * G_STAGE)

__device__ __forceinline__ void g_load_A(
    const __half* __restrict__ G, uint32_t sbase, int tid)
{
#pragma unroll
    for (int i = 0; i < 4; i++) {
        const int idx = tid + (i << 9);
        const int r = idx >> 3, s = idx & 7;
        cp16(sbase + (uint32_t)(r * ROWB + s * 16), G + (size_t)r * DM + s * 8);
    }
}
__device__ __forceinline__ void g_load_B(
    const __half* __restrict__ G, uint32_t sbase, int tid)
{
#pragma unroll
    for (int i = 0; i < 2; i++) {
        const int idx = tid + (i << 9);
        const int r = idx >> 3, s = idx & 7;
        cp16(sbase + (uint32_t)(r * ROWB + s * 16), G + (size_t)r * DM + s * 8);
    }
}

__global__ void __launch_bounds__(512, 1) gemm_f16(
    const __half* __restrict__ A, const __half* __restrict__ BT,
    const float* __restrict__ bias, void* __restrict__ Cout, int mode)
{
    extern __shared__ __align__(16) char smraw[];
    const uint32_t smem0 = (uint32_t)__cvta_generic_to_shared(smraw);

    const int tid  = threadIdx.x;
    const int wid  = tid >> 5, lane = tid & 31;
    const int wm   = wid >> 1, wn = wid & 1;
    const int g    = lane >> 2, kq = lane & 3;
    const int lrow = lane & 15;
    const int lcol = (lane >> 4) * 16;

    const int m0 = blockIdx.y * 256;
    const int n0 = blockIdx.x * 128;

    const __half* Ag = A  + (size_t)m0 * DM;
    const __half* Bg = BT + (size_t)n0 * DM;

    float c[2][8][4];
#pragma unroll
    for (int mt = 0; mt < 2; mt++)
#pragma unroll
        for (int nt = 0; nt < 8; nt++)
#pragma unroll
            for (int i = 0; i < 4; i++) c[mt][nt][i] = 0.f;

    g_load_A(Ag, smem0, tid);
    g_load_B(Bg, smem0 + GA_TILEB, tid);
    CP_COMMIT();
    g_load_A(Ag + 64, smem0 + G_STAGE, tid);
    g_load_B(Bg + 64, smem0 + G_STAGE + GA_TILEB, tid);
    CP_COMMIT();

    const int NCH = DM / 64;
    for (int kc = 0; kc < NCH; kc++) {
        if (kc < NCH - 1) { CP_WAIT(1); } else { CP_WAIT(0); }
        __syncthreads();

        if (kc + 2 < NCH) {
            const uint32_t sb = smem0 + (uint32_t)(((kc + 2) % 3) * G_STAGE);
            g_load_A(Ag + (kc + 2) * 64, sb, tid);
            g_load_B(Bg + (kc + 2) * 64, sb + GA_TILEB, tid);
            CP_COMMIT();
        }

        const uint32_t sA = smem0 + (uint32_t)((kc % 3) * G_STAGE);
        const uint32_t sB = sA + GA_TILEB;
        const uint32_t aBase = sA + (uint32_t)((wm * 32 + lrow) * ROWB) + lcol;
        const uint32_t bBase = sB + (uint32_t)((wn * 64 + lrow) * ROWB) + lcol;

#pragma unroll
        for (int ks = 0; ks < 4; ks++) {
            uint32_t af[2][4], bf[4][4];
#pragma unroll
            for (int mt = 0; mt < 2; mt++)
                ldm_x4(af[mt], aBase + (uint32_t)(mt * 16 * ROWB) + ks * 32);
#pragma unroll
            for (int np = 0; np < 4; np++)
                ldm_x4(bf[np], bBase + (uint32_t)(np * 16 * ROWB) + ks * 32);
#pragma unroll
            for (int mt = 0; mt < 2; mt++) {
#pragma unroll
                for (int np = 0; np < 4; np++) {
                    mma_f16(c[mt][2*np],   af[mt][0], af[mt][1], af[mt][2], af[mt][3],
                            bf[np][0], bf[np][2]);
                    mma_f16(c[mt][2*np+1], af[mt][0], af[mt][1], af[mt][2], af[mt][3],
                            bf[np][1], bf[np][3]);
                }
            }
        }
    }

#pragma unroll
    for (int mt = 0; mt < 2; mt++) {
        const int r1 = m0 + wm * 32 + mt * 16 + g;
        const int r2 = r1 + 8;
        const int b1 = r1 >> 11, s1 = r1 & 2047;
        const int b2 = r2 >> 11, s2 = r2 & 2047;
#pragma unroll
        for (int nt = 0; nt < 8; nt++) {
            const int n = n0 + wn * 64 + nt * 8 + 2 * kq;
            const float bx = bias[n], by = bias[n + 1];
            const float v10 = c[mt][nt][0] + bx, v11 = c[mt][nt][1] + by;
            const float v20 = c[mt][nt][2] + bx, v21 = c[mt][nt][3] + by;
            if (mode == 0) {
                __half* C = (__half*)Cout;
                const int which = n >> 10;
                const int nn = n & 1023;
                const int h = nn >> 6, d = nn & 63;
                const size_t base = (size_t)which * QKV_OFF;
                *(__half2*)(C + base + (((size_t)(b1 * NH + h)) * SEQ + s1) * DH + d) =
                    __floats2half2_rn(v10, v11);
                *(__half2*)(C + base + (((size_t)(b2 * NH + h)) * SEQ + s2) * DH + d) =
                    __floats2half2_rn(v20, v21);
            } else {
                float* C = (float*)Cout;
                *(float2*)(C + (size_t)r1 * DM + n) = make_float2(v10, v11);
                *(float2*)(C + (size_t)r2 * DM + n) = make_float2(v20, v21);
            }
        }
    }
}

// ===========================================================================
// Flash attention v4: f16-ACCUMULATE mma for QK and PV (2x tensor rate),
// f16x2 softmax (hmax2/hsub2/ex2), f32-acc ones-MMA for exact row sums,
// f32 master output accumulator folded per tile.
// 4 warps/block, m32/warp, q-tile 128, BK=128.
// ===========================================================================
#define FA_TILEB (128 * ROWB)
#define FA_SMEM (5 * FA_TILEB)

#define ONES_H2 0x3C003C00u

__device__ __forceinline__ void fa_load_tile(
    const __half* __restrict__ G, uint32_t sbase, int tid)
{
#pragma unroll
    for (int i = 0; i < 8; i++) {
        const int idx = tid + (i << 7);
        const int r = idx >> 3, s = idx & 7;
        cp16(sbase + (uint32_t)(r * ROWB + s * 16), G + (size_t)r * DH + s * 8);
    }
}

__global__ void __launch_bounds__(128) fa_mma(
    const __half* __restrict__ Q, const __half* __restrict__ K,
    const __half* __restrict__ V, __half* __restrict__ Out)
{
    extern __shared__ __align__(16) char smraw[];
    const uint32_t smem0 = (uint32_t)__cvta_generic_to_shared(smraw);
    const uint32_t smQ = smem0;

    const int tid = threadIdx.x;
    const int wid = tid >> 5, lane = tid & 31;
    const int g = lane >> 2, kq = lane & 3;
    const int lrow = lane & 15;
    const int lcol = (lane >> 4) * 16;

    const int q0 = blockIdx.x * 128;
    const int bh = blockIdx.y;
    const int b = bh >> 4, h = bh & 15;

    const __half* Qg = Q + (size_t)bh * SEQ * DH + (size_t)q0 * DH;
    const __half* Kg = K + (size_t)bh * SEQ * DH;
    const __half* Vg = V + (size_t)bh * SEQ * DH;

    fa_load_tile(Qg, smQ, tid);
    CP_COMMIT();
    fa_load_tile(Kg, smem0 + 1 * FA_TILEB, tid);
    fa_load_tile(Vg, smem0 + 3 * FA_TILEB, tid);
    CP_COMMIT();

    __half mxh[2][2];
    float li[2][2];
    float co[2][8][4];
#pragma unroll
    for (int mh = 0; mh < 2; mh++) {
        mxh[mh][0] = mxh[mh][1] = __float2half(-INFINITY);
        li[mh][0] = li[mh][1] = 0.f;
#pragma unroll
        for (int nt = 0; nt < 8; nt++)
#pragma unroll
            for (int i = 0; i < 4; i++) co[mh][nt][i] = 0.f;
    }

    const uint32_t qBase = smQ + (uint32_t)((wid * 32 + lrow) * ROWB) + lcol;

    for (int t = 0; t < SEQ / 128; t++) {
        __syncthreads();
        if (t + 1 < SEQ / 128) {
            const uint32_t koff = ((t + 1) & 1) ? 2u : 1u;
            fa_load_tile(Kg + (size_t)(t + 1) * 128 * DH, smem0 + koff * FA_TILEB, tid);
            fa_load_tile(Vg + (size_t)(t + 1) * 128 * DH, smem0 + (koff + 2) * FA_TILEB, tid);
            CP_COMMIT();
            CP_WAIT(1);
        } else {
            CP_WAIT(0);
        }
        __syncthreads();

        const uint32_t sK = smem0 + ((t & 1) ? 2u : 1u) * FA_TILEB;
        const uint32_t sV = smem0 + ((t & 1) ? 4u : 3u) * FA_TILEB;
        const uint32_t kBase = sK + (uint32_t)(lrow * ROWB) + lcol;
        const uint32_t vBase = sV + (uint32_t)(lrow * ROWB) + lcol;

        // ---- scores (log2 domain), f16 accumulate: S[32 x 128] = Q @ K^T ----
        uint32_t csh[2][16][2];
#pragma unroll
        for (int mh = 0; mh < 2; mh++)
#pragma unroll
            for (int nt = 0; nt < 16; nt++)
                csh[mh][nt][0] = csh[mh][nt][1] = 0u;

#pragma unroll
        for (int ks = 0; ks < 4; ks++) {
            uint32_t a[2][4];
            ldm_x4(a[0], qBase + ks * 32);
            ldm_x4(a[1], qBase + (uint32_t)(16 * ROWB) + ks * 32);
#pragma unroll
            for (int np = 0; np < 8; np++) {
                uint32_t bb[4];
                ldm_x4(bb, kBase + (uint32_t)(np * 16 * ROWB) + ks * 32);
#pragma unroll
                for (int mh = 0; mh < 2; mh++) {
                    mma_f16acc(csh[mh][2*np],   a[mh][0], a[mh][1], a[mh][2], a[mh][3],
                               bb[0], bb[2]);
                    mma_f16acc(csh[mh][2*np+1], a[mh][0], a[mh][1], a[mh][2], a[mh][3],
                               bb[1], bb[3]);
                }
            }
        }

        // ---- online softmax in f16x2; P = 2^(s-m) via ex2.f16x2 ----
        uint32_t p[2][16][2];
        float corr[2][2];
#pragma unroll
        for (int mh = 0; mh < 2; mh++) {
            __half2 v0 = *(__half2*)&csh[mh][0][0];
            __half2 v1 = *(__half2*)&csh[mh][0][1];
#pragma unroll
            for (int nt = 1; nt < 16; nt++) {
                v0 = __hmax2(v0, *(__half2*)&csh[mh][nt][0]);
                v1 = __hmax2(v1, *(__half2*)&csh[mh][nt][1]);
            }
            __half t0 = __hmax(__low2half(v0), __high2half(v0));
            __half t1 = __hmax(__low2half(v1), __high2half(v1));
            // cross-lane max over the 4 kq lanes (same row group)
#pragma unroll
            for (int off = 1; off <= 2; off <<= 1) {
                uint32_t u0 = (uint32_t)__half_as_ushort(t0);
                uint32_t u1 = (uint32_t)__half_as_ushort(t1);
                u0 = __shfl_xor_sync(0xffffffffu, u0, off);
                u1 = __shfl_xor_sync(0xffffffffu, u1, off);
                t0 = __hmax(t0, __ushort_as_half((unsigned short)u0));
                t1 = __hmax(t1, __ushort_as_half((unsigned short)u1));
            }
            const __half mn0 = __hmax(mxh[mh][0], t0);
            const __half mn1 = __hmax(mxh[mh][1], t1);
            corr[mh][0] = exp2f(__half2float(mxh[mh][0]) - __half2float(mn0));
            corr[mh][1] = exp2f(__half2float(mxh[mh][1]) - __half2float(mn1));
            mxh[mh][0] = mn0; mxh[mh][1] = mn1;

            const __half2 b0h = __half2half2(mn0);
            const __half2 b1h = __half2half2(mn1);
            const uint32_t b0u = *(uint32_t*)&b0h;
            const uint32_t b1u = *(uint32_t*)&b1h;
#pragma unroll
            for (int nt = 0; nt < 16; nt++) {
                p[mh][nt][0] = ex2_h2(hsub2_u(csh[mh][nt][0], b0u));
                p[mh][nt][1] = ex2_h2(hsub2_u(csh[mh][nt][1], b1u));
            }
        }

        // ---- PV (f16 acc, fresh per tile) + exact row-sum via f32-acc ones-MMA ----
        uint32_t cot[2][8][2];
        float lacc[2][4];
#pragma unroll
        for (int mh = 0; mh < 2; mh++) {
#pragma unroll
            for (int nt = 0; nt < 8; nt++) cot[mh][nt][0] = cot[mh][nt][1] = 0u;
#pragma unroll
            for (int i = 0; i < 4; i++) lacc[mh][i] = 0.f;
        }

#pragma unroll
        for (int j = 0; j < 8; j++) {
            uint32_t bb[4][4];
#pragma unroll
            for (int np = 0; np < 4; np++)
                ldm_x4t(bb[np], vBase + (uint32_t)(j * 16 * ROWB) + np * 32);
#pragma unroll
            for (int mh = 0; mh < 2; mh++) {
                const uint32_t a0 = p[mh][2*j][0];
                const uint32_t a1 = p[mh][2*j][1];
                const uint32_t a2 = p[mh][2*j+1][0];
                const uint32_t a3 = p[mh][2*j+1][1];
#pragma unroll
                for (int np = 0; np < 4; np++) {
                    mma_f16acc(cot[mh][2*np],   a0, a1, a2, a3, bb[np][0], bb[np][1]);
                    mma_f16acc(cot[mh][2*np+1], a0, a1, a2, a3, bb[np][2], bb[np][3]);
                }
                mma_f16(lacc[mh], a0, a1, a2, a3, ONES_H2, ONES_H2);
            }
        }

        // ---- fold tile results into f32 masters ----
#pragma unroll
        for (int mh = 0; mh < 2; mh++) {
#pragma unroll
            for (int nt = 0; nt < 8; nt++) {
                const float2 lo = __half22float2(*(__half2*)&cot[mh][nt][0]);
                const float2 hi = __half22float2(*(__half2*)&cot[mh][nt][1]);
                co[mh][nt][0] = co[mh][nt][0] * corr[mh][0] + lo.x;
                co[mh][nt][1] = co[mh][nt][1] * corr[mh][0] + lo.y;
                co[mh][nt][2] = co[mh][nt][2] * corr[mh][1] + hi.x;
                co[mh][nt][3] = co[mh][nt][3] * corr[mh][1] + hi.y;
            }
            li[mh][0] = li[mh][0] * corr[mh][0] + lacc[mh][0];
            li[mh][1] = li[mh][1] * corr[mh][1] + lacc[mh][2];
        }
    }

    // ---- epilogue: normalize, write fp16 [B, S, H*dh] ----
#pragma unroll
    for (int mh = 0; mh < 2; mh++) {
        const float inv0 = 1.f / li[mh][0], inv1 = 1.f / li[mh][1];
        const int qrow = wid * 32 + mh * 16 + g;
        __half* Og = Out + ((size_t)b * SEQ + (q0 + qrow)) * DM + h * DH;
#pragma unroll
        for (int nt = 0; nt < 8; nt++) {
            *(__half2*)(Og + 8 * nt + 2 * kq) =
                __floats2half2_rn(co[mh][nt][0] * inv0, co[mh][nt][1] * inv0);
            *(__half2*)(Og + (size_t)8 * DM + 8 * nt + 2 * kq) =
                __floats2half2_rn(co[mh][nt][2] * inv1, co[mh][nt][3] * inv1);
        }
    }
}

// ---------------------------------------------------------------------------
// Launch
// ---------------------------------------------------------------------------
extern "C" void kernel_launch(void* const* d_in, const int* in_sizes, int n_in,
                              void* d_out, int out_size)
{
    const float* x  = (const float*)d_in[0];
    // d_in[1] = pH : constant along softmax axis -> provably no effect
    const float* Wq = (const float*)d_in[2];
    const float* bq = (const float*)d_in[3];
    const float* Wk = (const float*)d_in[4];
    const float* bk = (const float*)d_in[5];
    const float* Wv = (const float*)d_in[6];
    const float* bv = (const float*)d_in[7];
    const float* Wo = (const float*)d_in[8];
    const float* bo = (const float*)d_in[9];
    float* out = (float*)d_out;

    __half *x16, *qkv, *att, *wt, *wto;
    float *bias;
    cudaGetSymbolAddress((void**)&x16,  g_X16);
    cudaGetSymbolAddress((void**)&qkv,  g_QKV);
    cudaGetSymbolAddress((void**)&att,  g_ATT);
    cudaGetSymbolAddress((void**)&wt,   g_WT);
    cudaGetSymbolAddress((void**)&wto,  g_WTO);
    cudaGetSymbolAddress((void**)&bias, g_BIAS);

    cudaFuncSetAttribute(gemm_f16, cudaFuncAttributeMaxDynamicSharedMemorySize, G_SMEM);
    cudaFuncSetAttribute(fa_mma, cudaFuncAttributeMaxDynamicSharedMemorySize, FA_SMEM);

    // Fused prep: f2h + 4 transposes + bias pack (log2e folded into Wq/bq)
    prep<<<5121, 256>>>(x, Wq, Wk, Wv, Wo, bq, bk, bv, x16, wt, wto, bias);

    // Merged QKV projection: N = 3072
    dim3 gq(3 * DM / 128, MROWS / 256);   // (24, 16)
    gemm_f16<<<gq, 512, G_SMEM>>>(x16, wt, bias, qkv, 0);

    // Attention
    dim3 ga(SEQ / 128, BATCH * NH);       // (16, 32)
    fa_mma<<<ga, 128, FA_SMEM>>>(qkv, qkv + QKV_OFF, qkv + 2 * QKV_OFF, att);

    // Output projection (fp32 out)
    dim3 go(DM / 128, MROWS / 256);       // (8, 16)
    gemm_f16<<<go, 512, G_SMEM>>>(att, wto, bo, out, 1);
}